// round 12
// baseline (speedup 1.0000x reference)
#include <cuda_runtime.h>
#include <cuda_fp16.h>
#include <cstdint>

#define B_  2
#define L_  4096
#define D_  1024
#define BL_ 8192        // B_*L_
#define NU_ 2048        // kept columns of GEMM1 (stream0 + stream2)

// ---------------- scratch (static device globals; no allocation) ----------------
__device__ float g_U [(size_t)BL_ * NU_];        // GEMM1 out: [b*L+l][2048] fp32
__device__ float g_h [D_];
__device__ int   g_hnz;
__device__ __half g_Xh [(size_t)BL_ * D_];   // x split hi (fp16)
__device__ __half g_Xl [(size_t)BL_ * D_];   // x split lo
__device__ __half g_Zth[(size_t)BL_ * D_];   // z (as [m][k]) split hi
__device__ __half g_Ztl[(size_t)BL_ * D_];
__device__ __half g_W1 [(size_t)NU_ * D_];   // w_in kept cols, [n][k], single fp16
__device__ __half g_W2 [(size_t)D_ * D_];    // w_out, [n][k], single fp16
__device__ float g_biasg[NU_];

// ---------------- PTX helpers (arch-generic: sm_80+ features only) ----------------
__device__ __forceinline__ uint32_t smem_u32(const void* p) {
    uint32_t a;
    asm("{ .reg .u64 t; cvta.to.shared.u64 t, %1; cvt.u32.u64 %0, t; }" : "=r"(a) : "l"(p));
    return a;
}
__device__ __forceinline__ uint32_t swz(uint32_t o) { return o ^ ((o >> 3) & 0x70); }
__device__ __forceinline__ void cp16(uint32_t s, const void* g) {
    asm volatile("cp.async.cg.shared.global [%0], [%1], 16;" :: "r"(s), "l"(g));
}
__device__ __forceinline__ void cp_commit() {
    asm volatile("cp.async.commit_group;");
}
template <int N>
__device__ __forceinline__ void cp_wait() {
    asm volatile("cp.async.wait_group %0;" :: "n"(N));
}
__device__ __forceinline__ void ldsm4(uint32_t& r0, uint32_t& r1, uint32_t& r2, uint32_t& r3,
                                      uint32_t addr) {
    asm volatile("ldmatrix.sync.aligned.m8n8.x4.shared.b16 {%0,%1,%2,%3}, [%4];"
                 : "=r"(r0), "=r"(r1), "=r"(r2), "=r"(r3) : "r"(addr));
}
__device__ __forceinline__ void mma16816(float& c0, float& c1, float& c2, float& c3,
                                         uint32_t a0, uint32_t a1, uint32_t a2, uint32_t a3,
                                         uint32_t b0, uint32_t b1) {
    asm volatile("mma.sync.aligned.m16n8k16.row.col.f32.f16.f16.f32 "
                 "{%0,%1,%2,%3}, {%4,%5,%6,%7}, {%8,%9}, {%0,%1,%2,%3};"
                 : "+f"(c0), "+f"(c1), "+f"(c2), "+f"(c3)
                 : "r"(a0), "r"(a1), "r"(a2), "r"(a3), "r"(b0), "r"(b1));
}

// =====================================================================
// split-fp16 2-pass GEMM via ldmatrix + mma.sync (HMMA).
//   C[M x N] = Ah*B + Al*B  (+bias),  K = 1024
// BK=64 chunks (16 iters), SW128 XOR-swizzled smem, 2 stages, one
// __syncthreads per chunk, depth-1 prefetch into the stage freed by the
// previous iteration.  Per kk: ALL fragments (B, A-hi, A-lo) loaded
// upfront, then both MMA passes issue back-to-back (no mid-sequence
// ldsm scoreboard bubble).
// TM=128: 8 warps 4(m)x2(n), warp tile 32x64, 2 CTAs/SM  (GEMM1 — best
//         ldsm:MMA ratio, L1 traffic per FLOP 1.5x lower than TM=64).
// TM=64 : 8 warps 2(m)x4(n), warp tile 32x32, 3 CTAs/SM  (GEMM2).
// WHICH=0: GEMM1 (Xh/Xl x W1 -> g_U, bias g_biasg, ldc 2048)
// WHICH=1: GEMM2 (Zt x W2 -> out, bias param, ldc 1024)
// =====================================================================
template <int WHICH, int TM>
__global__ __launch_bounds__(256, TM == 128 ? 2 : 3)
void gemm_mma(const float* __restrict__ bias_p, float* __restrict__ C_p) {
    constexpr int WM_CNT = (TM == 128) ? 4 : 2;     // warps along M
    constexpr int WT_N   = 128 / (8 / WM_CNT);      // warp tile N (64 or 32)
    constexpr int NI     = WT_N / 8;                // n-frags per warp (8 or 4)
    constexpr int ATILE_B = TM * 128;               // bytes per A tile
    constexpr int BTILE_B = 16384;                  // 128x64 fp16
    constexpr int STAGE_H = (2 * ATILE_B + BTILE_B) / 2;

    __shared__ __align__(1024) __half sm[2][STAGE_H];   // AH|AL|B per stage

    const int tid = threadIdx.x;
    const int lane = tid & 31;
    const int wid = tid >> 5;
    const int warp_m = wid % WM_CNT;
    const int warp_n = wid / WM_CNT;
    const int m0 = blockIdx.y * TM;
    const int n0 = blockIdx.x * 128;

    const __half* __restrict__ Ah = WHICH ? g_Zth : g_Xh;
    const __half* __restrict__ Al = WHICH ? g_Ztl : g_Xl;
    const __half* __restrict__ Bw = WHICH ? g_W2 : g_W1;
    const float* __restrict__ bias = WHICH ? bias_p : g_biasg;
    float* __restrict__ C = WHICH ? C_p : g_U;
    const int ldc = WHICH ? 1024 : 2048;

    const __half* gpA[2] = {Ah, Al};

    uint32_t sA = smem_u32(sm[0]);      // compute stage
    uint32_t sB = smem_u32(sm[1]);      // prefetch stage

    float acc[2][NI][4];
#pragma unroll
    for (int i = 0; i < 2; i++)
#pragma unroll
        for (int j = 0; j < NI; j++)
#pragma unroll
            for (int q = 0; q < 4; q++) acc[i][j][q] = 0.f;

    // ldmatrix lane->local-row maps
    const int a_loc = (lane & 7) + ((lane >> 3) & 1) * 8;   // m0k0,m8k0,m0k8,m8k8
    const int a_kb  = (lane >> 4) * 16;                     // bytes
    const int b_loc = (lane & 7) + ((lane >> 4) & 1) * 8;   // n0k0,n0k8,n8k0,n8k8
    const int b_kb  = ((lane >> 3) & 1) * 16;               // bytes

    auto load_chunk = [&](uint32_t dst, int k0) {
#pragma unroll
        for (int t = 0; t < 2; t++) {                       // A tiles (TM rows)
#pragma unroll
            for (int j = 0; j < TM / 32; j++) {
                const int id = tid + j * 256;
                const int row = id >> 3, seg = id & 7;
                cp16(dst + t * ATILE_B + swz(row * 128 + seg * 16),
                     gpA[t] + (size_t)(m0 + row) * 1024 + k0 + seg * 8);
            }
        }
#pragma unroll
        for (int j = 0; j < 4; j++) {                       // B tile (128 rows)
            const int id = tid + j * 256;
            const int row = id >> 3, seg = id & 7;
            cp16(dst + 2 * ATILE_B + swz(row * 128 + seg * 16),
                 Bw + (size_t)(n0 + row) * 1024 + k0 + seg * 8);
        }
        cp_commit();
    };

    load_chunk(sA, 0);

#pragma unroll 1
    for (int kc = 0; kc < 16; kc++) {
        cp_wait<0>();
        __syncthreads();                 // publish chunk kc; anti-WAR for sB

        if (kc + 1 < 16) load_chunk(sB, (kc + 1) * 64);

#pragma unroll
        for (int kk = 0; kk < 4; kk++) {
            const uint32_t kbase = kk * 32;           // bytes within 128B row
            // ---- ALL fragment loads upfront ----
            uint32_t bh[NI][2];
#pragma unroll
            for (int nj = 0; nj < NI / 2; nj++) {
                uint32_t r0, r1, r2, r3;
                ldsm4(r0, r1, r2, r3, sA + 2 * ATILE_B
                      + swz((warp_n * WT_N + nj * 16 + b_loc) * 128 + kbase + b_kb));
                bh[nj * 2 + 0][0] = r0; bh[nj * 2 + 0][1] = r1;
                bh[nj * 2 + 1][0] = r2; bh[nj * 2 + 1][1] = r3;
            }
            uint32_t ahi[2][4], alo[2][4];
#pragma unroll
            for (int mi = 0; mi < 2; mi++)
                ldsm4(ahi[mi][0], ahi[mi][1], ahi[mi][2], ahi[mi][3],
                      sA + swz((warp_m * 32 + mi * 16 + a_loc) * 128 + kbase + a_kb));
#pragma unroll
            for (int mi = 0; mi < 2; mi++)
                ldsm4(alo[mi][0], alo[mi][1], alo[mi][2], alo[mi][3],
                      sA + ATILE_B + swz((warp_m * 32 + mi * 16 + a_loc) * 128 + kbase + a_kb));
            // ---- both MMA passes back-to-back ----
#pragma unroll
            for (int mi = 0; mi < 2; mi++)
#pragma unroll
                for (int ni = 0; ni < NI; ni++)
                    mma16816(acc[mi][ni][0], acc[mi][ni][1], acc[mi][ni][2], acc[mi][ni][3],
                             ahi[mi][0], ahi[mi][1], ahi[mi][2], ahi[mi][3],
                             bh[ni][0], bh[ni][1]);
#pragma unroll
            for (int mi = 0; mi < 2; mi++)
#pragma unroll
                for (int ni = 0; ni < NI; ni++)
                    mma16816(acc[mi][ni][0], acc[mi][ni][1], acc[mi][ni][2], acc[mi][ni][3],
                             alo[mi][0], alo[mi][1], alo[mi][2], alo[mi][3],
                             bh[ni][0], bh[ni][1]);
        }
        const uint32_t tmp = sA; sA = sB; sB = tmp;
    }

    // ---- epilogue: m16n8 C frag: c0,c1 @ (lane>>2, (lane&3)*2), c2,c3 @ row+8
    const int er = lane >> 2;
    const int ec = (lane & 3) * 2;
#pragma unroll
    for (int mi = 0; mi < 2; mi++) {
#pragma unroll
        for (int ni = 0; ni < NI; ni++) {
            const int row = m0 + warp_m * 32 + mi * 16 + er;
            const int col = n0 + warp_n * WT_N + ni * 8 + ec;
            float2 o0 = make_float2(acc[mi][ni][0] + bias[col], acc[mi][ni][1] + bias[col + 1]);
            float2 o1 = make_float2(acc[mi][ni][2] + bias[col], acc[mi][ni][3] + bias[col + 1]);
            *(float2*)&C[(size_t)row * ldc + col] = o0;
            *(float2*)&C[(size_t)(row + 8) * ldc + col] = o1;
        }
    }
}

// =====================================================================
// Operand prep
// =====================================================================
__device__ __forceinline__ void split2h(float v, __half& h, __half& l) {
    h = __float2half(v);
    l = __float2half(v - __half2float(h));
}

__global__ __launch_bounds__(256)
void split_x_kernel(const float* __restrict__ x) {
    const size_t i4 = ((size_t)blockIdx.x * 256 + threadIdx.x) * 4;
    float4 v = *(const float4*)(x + i4);
    __half h[4], l[4];
    split2h(v.x, h[0], l[0]); split2h(v.y, h[1], l[1]);
    split2h(v.z, h[2], l[2]); split2h(v.w, h[3], l[3]);
    *(uint2*)(g_Xh + i4) = *(uint2*)h;
    *(uint2*)(g_Xl + i4) = *(uint2*)l;
}

// transpose + round BOTH weights to fp16 in ONE launch.
__global__ __launch_bounds__(256)
void prep_w_all(const float* __restrict__ w_in, const float* __restrict__ w_out) {
    const int bx = blockIdx.x;
    const bool is1 = (bx < 64);
    const float* __restrict__ W = is1 ? w_in : w_out;
    __half* __restrict__ o = is1 ? g_W1 : g_W2;
    const int src_ld = is1 ? 3072 : 1024;
    const int n0 = (is1 ? bx : bx - 64) * 32;
    const int cbase = n0 + ((is1 && n0 >= 1024) ? 1024 : 0);
    const int k0 = blockIdx.y * 32;
    __shared__ float t[32][33];
    const int x = threadIdx.x, y = threadIdx.y;
#pragma unroll
    for (int j = 0; j < 4; j++)
        t[y + 8 * j][x] = W[(size_t)(k0 + y + 8 * j) * src_ld + cbase + x];
    __syncthreads();
#pragma unroll
    for (int j = 0; j < 4; j++)
        o[(size_t)(n0 + y + 8 * j) * 1024 + k0 + x] = __float2half(t[x][y + 8 * j]);
}

// =====================================================================
// Filter generation (row 0 only; t[0]==0 so w1 drops out) + bias gather
// =====================================================================
__device__ __forceinline__ float silu_f(float v) { return v / (1.f + __expf(-v)); }

__global__ void filtgen_kernel(const float* __restrict__ b1, const float* __restrict__ w2,
                               const float* __restrict__ b2, const float* __restrict__ w3,
                               const float* __restrict__ b_in) {
    __shared__ float m1[64], m2[64];
    __shared__ int flag;
    const int t = threadIdx.x;          // 1024 threads
    g_biasg[t] = b_in[t];
    g_biasg[t + 1024] = b_in[t + 2048];
    if (t == 0) flag = 0;
    if (t < 64) m1[t] = silu_f(b1[t]);
    __syncthreads();
    if (t < 64) {
        float a = b2[t];
#pragma unroll
        for (int i = 0; i < 64; i++) a += m1[i] * w2[i * 64 + t];
        m2[t] = silu_f(a);
    }
    __syncthreads();
    float a = 0.f;
#pragma unroll
    for (int j = 0; j < 64; j++) a += m2[j] * w3[j * 1024 + t];
    g_h[t] = a;
    if (a != 0.f) flag = 1;
    __syncthreads();
    if (t == 0) g_hnz = flag;
}

// =====================================================================
// FAST PATH (h == 0): fused depthwise conv + gate + pointwise "fir" +
// transpose-to-[m][k] + fp16 split, l-tiled with register rotation so
// g_U is read exactly once.  z = s0^2 * s2 * fb[d].
// =====================================================================
__global__ __launch_bounds__(256)
void fuse_fast_kernel(const float* __restrict__ wc, const float* __restrict__ bc,
                      const float* __restrict__ fb) {
    if (g_hnz != 0) return;
    const int l0 = blockIdx.x * 32, b = blockIdx.y;
    const int d4 = threadIdx.x * 4;
    const float* ub = g_U + ((size_t)(b * L_ + l0)) * NU_;
    const float4 zero = make_float4(0.f, 0.f, 0.f, 0.f);

    float c0t[3][4], c2t[3][4], b0v[4], b2v[4], fbv[4];
#pragma unroll
    for (int j = 0; j < 4; j++) {
        const int d = d4 + j, d2 = d + 2048;
        c0t[0][j] = wc[d * 3]; c0t[1][j] = wc[d * 3 + 1]; c0t[2][j] = wc[d * 3 + 2];
        c2t[0][j] = wc[d2 * 3]; c2t[1][j] = wc[d2 * 3 + 1]; c2t[2][j] = wc[d2 * 3 + 2];
        b0v[j] = bc[d]; b2v[j] = bc[d2]; fbv[j] = fb[d];
    }

    float4 u0a = (l0 >= 2) ? *(const float4*)(ub - 2 * NU_ + d4) : zero;
    float4 u2a = (l0 >= 2) ? *(const float4*)(ub - 2 * NU_ + 1024 + d4) : zero;
    float4 u0b = (l0 >= 1) ? *(const float4*)(ub - NU_ + d4) : zero;
    float4 u2b = (l0 >= 1) ? *(const float4*)(ub - NU_ + 1024 + d4) : zero;

#pragma unroll 4
    for (int i = 0; i < 32; i++) {
        float4 u0c = *(const float4*)(ub + (size_t)i * NU_ + d4);
        float4 u2c = *(const float4*)(ub + (size_t)i * NU_ + 1024 + d4);
        const float* p0a = &u0a.x; const float* p0b = &u0b.x; const float* p0c = &u0c.x;
        const float* p2a = &u2a.x; const float* p2b = &u2b.x; const float* p2c = &u2c.x;

        __half h[4], lo[4];
#pragma unroll
        for (int j = 0; j < 4; j++) {
            float s0 = c0t[0][j] * p0a[j] + c0t[1][j] * p0b[j] + c0t[2][j] * p0c[j] + b0v[j];
            float s2 = c2t[0][j] * p2a[j] + c2t[1][j] * p2b[j] + c2t[2][j] * p2c[j] + b2v[j];
            float z = s0 * s0 * s2 * fbv[j];
            split2h(z, h[j], lo[j]);
        }
        const size_t o = ((size_t)(b * L_ + l0 + i)) * 1024 + d4;
        *(uint2*)(g_Zth + o) = *(uint2*)h;
        *(uint2*)(g_Ztl + o) = *(uint2*)lo;

        u0a = u0b; u0b = u0c;
        u2a = u2b; u2b = u2c;
    }
}

// =====================================================================
// SLOW PATH (h != 0) — correctness fallback merged into ONE kernel.
// Inactive for this benchmark (h==0) — exits immediately.
// =====================================================================
__global__ __launch_bounds__(256)
void slow_path_kernel(const float* __restrict__ wc, const float* __restrict__ bc,
                      const float* __restrict__ fb) {
    if (g_hnz == 0) return;
    const int row = blockIdx.x;          // b*D + d
    const int b = row >> 10;
    const int d = row & (D_ - 1);
    const int d2 = d + 2048;
    const float c00 = wc[d * 3], c01 = wc[d * 3 + 1], c02 = wc[d * 3 + 2];
    const float c20 = wc[d2 * 3], c21 = wc[d2 * 3 + 1], c22 = wc[d2 * 3 + 2];
    const float b0v = bc[d], b2v = bc[d2], fbd = fb[d];

    __shared__ float hs[1024];
    __shared__ float s0s[4096];
    __shared__ float vs[1040 + 4096];    // 1040 leading zeros = causal padding

    for (int i = threadIdx.x; i < 1024; i += 256) hs[i] = g_h[i];
    for (int i = threadIdx.x; i < 1040; i += 256) vs[i] = 0.f;

    const float* Ub = g_U + (size_t)(b * L_) * NU_;
    for (int l = threadIdx.x; l < L_; l += 256) {
        float u0c = Ub[(size_t)l * NU_ + d];
        float u2c = Ub[(size_t)l * NU_ + 1024 + d];
        float u0b = (l >= 1) ? Ub[(size_t)(l - 1) * NU_ + d] : 0.f;
        float u2b = (l >= 1) ? Ub[(size_t)(l - 1) * NU_ + 1024 + d] : 0.f;
        float u0a = (l >= 2) ? Ub[(size_t)(l - 2) * NU_ + d] : 0.f;
        float u2a = (l >= 2) ? Ub[(size_t)(l - 2) * NU_ + 1024 + d] : 0.f;
        float s0 = c00 * u0a + c01 * u0b + c02 * u0c + b0v;
        float s2 = c20 * u2a + c21 * u2b + c22 * u2c + b2v;
        s0s[l] = s0;
        vs[1040 + l] = s0 * s2;
    }
    __syncthreads();

    const int l0 = threadIdx.x * 16;
    float acc[16];
#pragma unroll
    for (int i = 0; i < 16; i++) acc[i] = 0.f;
#pragma unroll 1
    for (int j0 = 0; j0 < 1024; j0 += 16) {
        float hh[16];
#pragma unroll
        for (int jj = 0; jj < 16; jj++) hh[jj] = hs[j0 + jj];
        float w[31];
        const int base = 1040 + l0 - j0 - 15;
#pragma unroll
        for (int k = 0; k < 31; k++) w[k] = vs[base + k];
#pragma unroll
        for (int i = 0; i < 16; i++)
#pragma unroll
            for (int jj = 0; jj < 16; jj++)
                acc[i] += hh[jj] * w[15 + i - jj];
    }
#pragma unroll
    for (int i = 0; i < 16; i++) {
        const int l = l0 + i;
        const float z = (acc[i] + vs[1040 + l] * fbd) * s0s[l];
        __half h, lo; split2h(z, h, lo);
        const size_t o = ((size_t)(b * L_ + l)) * 1024 + d;
        g_Zth[o] = h; g_Ztl[o] = lo;
    }
}

// =====================================================================
extern "C" void kernel_launch(void* const* d_in, const int* in_sizes, int n_in,
                              void* d_out, int out_size) {
    const float* x      = (const float*)d_in[0];
    const float* w_in   = (const float*)d_in[1];
    const float* b_in   = (const float*)d_in[2];
    const float* w_conv = (const float*)d_in[3];
    const float* b_conv = (const float*)d_in[4];
    // d_in[5] = w1 (multiplied by t[0]==0; unused for filters[0])
    const float* b1     = (const float*)d_in[6];
    const float* w2     = (const float*)d_in[7];
    const float* b2     = (const float*)d_in[8];
    const float* w3     = (const float*)d_in[9];
    const float* fbias  = (const float*)d_in[10];
    const float* w_out  = (const float*)d_in[11];
    const float* b_out  = (const float*)d_in[12];
    float* out = (float*)d_out;

    split_x_kernel<<<BL_ * D_ / 1024, 256>>>(x);
    prep_w_all<<<dim3(96, 32), dim3(32, 8)>>>(w_in, w_out);
    filtgen_kernel<<<1, 1024>>>(b1, w2, b2, w3, b_in);

    gemm_mma<0, 128><<<dim3(NU_ / 128, BL_ / 128), 256>>>(nullptr, nullptr);

    // slow path (no-op when h == 0)
    slow_path_kernel<<<B_ * D_, 256>>>(w_conv, b_conv, fbias);
    // fast path (no-op when h != 0)
    fuse_fast_kernel<<<dim3(L_ / 32, B_), 256>>>(w_conv, b_conv, fbias);

    gemm_mma<1, 64><<<dim3(1024 / 128, BL_ / 64), 256>>>(b_out, out);
}

// round 13
// speedup vs baseline: 1.0202x; 1.0202x over previous
#include <cuda_runtime.h>
#include <cuda_fp16.h>
#include <cstdint>

#define B_  2
#define L_  4096
#define D_  1024
#define BL_ 8192        // B_*L_
#define NU_ 2048        // kept columns of GEMM1 (stream0 + stream2)

// ---------------- scratch (static device globals; no allocation) ----------------
__device__ float g_U [(size_t)BL_ * NU_];        // GEMM1 out: [b*L+l][2048] fp32
__device__ float g_h [D_];
__device__ int   g_hnz;
__device__ __half g_Xh [(size_t)BL_ * D_];   // x split hi (fp16)
__device__ __half g_Xl [(size_t)BL_ * D_];   // x split lo
__device__ __half g_Zth[(size_t)BL_ * D_];   // z (as [m][k]) split hi
__device__ __half g_Ztl[(size_t)BL_ * D_];
__device__ __half g_W1 [(size_t)NU_ * D_];   // w_in kept cols, [n][k], single fp16
__device__ __half g_W2 [(size_t)D_ * D_];    // w_out, [n][k], single fp16
__device__ float g_biasg[NU_];

// ---------------- PTX helpers (arch-generic: sm_80+ features only) ----------------
__device__ __forceinline__ uint32_t smem_u32(const void* p) {
    uint32_t a;
    asm("{ .reg .u64 t; cvta.to.shared.u64 t, %1; cvt.u32.u64 %0, t; }" : "=r"(a) : "l"(p));
    return a;
}
__device__ __forceinline__ uint32_t swz(uint32_t o) { return o ^ ((o >> 3) & 0x70); }
__device__ __forceinline__ void cp16(uint32_t s, const void* g) {
    asm volatile("cp.async.cg.shared.global [%0], [%1], 16;" :: "r"(s), "l"(g));
}
__device__ __forceinline__ void cp_commit() {
    asm volatile("cp.async.commit_group;");
}
template <int N>
__device__ __forceinline__ void cp_wait() {
    asm volatile("cp.async.wait_group %0;" :: "n"(N));
}
__device__ __forceinline__ void ldsm4(uint32_t& r0, uint32_t& r1, uint32_t& r2, uint32_t& r3,
                                      uint32_t addr) {
    asm volatile("ldmatrix.sync.aligned.m8n8.x4.shared.b16 {%0,%1,%2,%3}, [%4];"
                 : "=r"(r0), "=r"(r1), "=r"(r2), "=r"(r3) : "r"(addr));
}
__device__ __forceinline__ void mma16816(float& c0, float& c1, float& c2, float& c3,
                                         uint32_t a0, uint32_t a1, uint32_t a2, uint32_t a3,
                                         uint32_t b0, uint32_t b1) {
    asm volatile("mma.sync.aligned.m16n8k16.row.col.f32.f16.f16.f32 "
                 "{%0,%1,%2,%3}, {%4,%5,%6,%7}, {%8,%9}, {%0,%1,%2,%3};"
                 : "+f"(c0), "+f"(c1), "+f"(c2), "+f"(c3)
                 : "r"(a0), "r"(a1), "r"(a2), "r"(a3), "r"(b0), "r"(b1));
}

// =====================================================================
// split-fp16 2-pass GEMM via ldmatrix + mma.sync (HMMA).
//   C[M x N] = Ah*B + Al*B  (+bias),  K = 1024
// BK=64 chunks (16 iters), SW128 XOR-swizzled smem, 2 stages, one
// __syncthreads per chunk, depth-1 prefetch into the stage freed by the
// previous iteration.  INTERLEAVED fragment order (measured best: hoisting
// all ldsm upfront regressed ~3% from register-pressure scheduling loss):
//   B-ldsm, A-hi-ldsm -> MMA(hi), A-lo-ldsm -> MMA(lo).
// TM=128: 8 warps 4(m)x2(n), warp tile 32x64, 2 CTAs/SM  (GEMM1 — best
//         ldsm:MMA ratio, L1 traffic per FLOP 1.5x lower than TM=64).
// TM=64 : 8 warps 2(m)x4(n), warp tile 32x32, 3 CTAs/SM  (GEMM2).
// WHICH=0: GEMM1 (Xh/Xl x W1 -> g_U, bias g_biasg, ldc 2048)
// WHICH=1: GEMM2 (Zt x W2 -> out, bias param, ldc 1024)
// =====================================================================
template <int WHICH, int TM>
__global__ __launch_bounds__(256, TM == 128 ? 2 : 3)
void gemm_mma(const float* __restrict__ bias_p, float* __restrict__ C_p) {
    constexpr int WM_CNT = (TM == 128) ? 4 : 2;     // warps along M
    constexpr int WT_N   = 128 / (8 / WM_CNT);      // warp tile N (64 or 32)
    constexpr int NI     = WT_N / 8;                // n-frags per warp (8 or 4)
    constexpr int ATILE_B = TM * 128;               // bytes per A tile
    constexpr int BTILE_B = 16384;                  // 128x64 fp16
    constexpr int STAGE_H = (2 * ATILE_B + BTILE_B) / 2;

    __shared__ __align__(1024) __half sm[2][STAGE_H];   // AH|AL|B per stage

    const int tid = threadIdx.x;
    const int lane = tid & 31;
    const int wid = tid >> 5;
    const int warp_m = wid % WM_CNT;
    const int warp_n = wid / WM_CNT;
    const int m0 = blockIdx.y * TM;
    const int n0 = blockIdx.x * 128;

    const __half* __restrict__ Ah = WHICH ? g_Zth : g_Xh;
    const __half* __restrict__ Al = WHICH ? g_Ztl : g_Xl;
    const __half* __restrict__ Bw = WHICH ? g_W2 : g_W1;
    const float* __restrict__ bias = WHICH ? bias_p : g_biasg;
    float* __restrict__ C = WHICH ? C_p : g_U;
    const int ldc = WHICH ? 1024 : 2048;

    const __half* gpA[2] = {Ah, Al};

    uint32_t sA = smem_u32(sm[0]);      // compute stage
    uint32_t sB = smem_u32(sm[1]);      // prefetch stage

    float acc[2][NI][4];
#pragma unroll
    for (int i = 0; i < 2; i++)
#pragma unroll
        for (int j = 0; j < NI; j++)
#pragma unroll
            for (int q = 0; q < 4; q++) acc[i][j][q] = 0.f;

    // ldmatrix lane->local-row maps
    const int a_loc = (lane & 7) + ((lane >> 3) & 1) * 8;   // m0k0,m8k0,m0k8,m8k8
    const int a_kb  = (lane >> 4) * 16;                     // bytes
    const int b_loc = (lane & 7) + ((lane >> 4) & 1) * 8;   // n0k0,n0k8,n8k0,n8k8
    const int b_kb  = ((lane >> 3) & 1) * 16;               // bytes

    auto load_chunk = [&](uint32_t dst, int k0) {
#pragma unroll
        for (int t = 0; t < 2; t++) {                       // A tiles (TM rows)
#pragma unroll
            for (int j = 0; j < TM / 32; j++) {
                const int id = tid + j * 256;
                const int row = id >> 3, seg = id & 7;
                cp16(dst + t * ATILE_B + swz(row * 128 + seg * 16),
                     gpA[t] + (size_t)(m0 + row) * 1024 + k0 + seg * 8);
            }
        }
#pragma unroll
        for (int j = 0; j < 4; j++) {                       // B tile (128 rows)
            const int id = tid + j * 256;
            const int row = id >> 3, seg = id & 7;
            cp16(dst + 2 * ATILE_B + swz(row * 128 + seg * 16),
                 Bw + (size_t)(n0 + row) * 1024 + k0 + seg * 8);
        }
        cp_commit();
    };

    load_chunk(sA, 0);

#pragma unroll 1
    for (int kc = 0; kc < 16; kc++) {
        cp_wait<0>();
        __syncthreads();                 // publish chunk kc; anti-WAR for sB

        if (kc + 1 < 16) load_chunk(sB, (kc + 1) * 64);

#pragma unroll
        for (int kk = 0; kk < 4; kk++) {
            const uint32_t kbase = kk * 32;           // bytes within 128B row
            // B fragments (shared by both passes)
            uint32_t bh[NI][2];
#pragma unroll
            for (int nj = 0; nj < NI / 2; nj++) {
                uint32_t r0, r1, r2, r3;
                ldsm4(r0, r1, r2, r3, sA + 2 * ATILE_B
                      + swz((warp_n * WT_N + nj * 16 + b_loc) * 128 + kbase + b_kb));
                bh[nj * 2 + 0][0] = r0; bh[nj * 2 + 0][1] = r1;
                bh[nj * 2 + 1][0] = r2; bh[nj * 2 + 1][1] = r3;
            }
            // A hi fragments -> MMA
            uint32_t a[2][4];
#pragma unroll
            for (int mi = 0; mi < 2; mi++)
                ldsm4(a[mi][0], a[mi][1], a[mi][2], a[mi][3],
                      sA + swz((warp_m * 32 + mi * 16 + a_loc) * 128 + kbase + a_kb));
#pragma unroll
            for (int mi = 0; mi < 2; mi++)
#pragma unroll
                for (int ni = 0; ni < NI; ni++)
                    mma16816(acc[mi][ni][0], acc[mi][ni][1], acc[mi][ni][2], acc[mi][ni][3],
                             a[mi][0], a[mi][1], a[mi][2], a[mi][3], bh[ni][0], bh[ni][1]);
            // A lo fragments -> MMA (reuse regs)
#pragma unroll
            for (int mi = 0; mi < 2; mi++)
                ldsm4(a[mi][0], a[mi][1], a[mi][2], a[mi][3],
                      sA + ATILE_B + swz((warp_m * 32 + mi * 16 + a_loc) * 128 + kbase + a_kb));
#pragma unroll
            for (int mi = 0; mi < 2; mi++)
#pragma unroll
                for (int ni = 0; ni < NI; ni++)
                    mma16816(acc[mi][ni][0], acc[mi][ni][1], acc[mi][ni][2], acc[mi][ni][3],
                             a[mi][0], a[mi][1], a[mi][2], a[mi][3], bh[ni][0], bh[ni][1]);
        }
        const uint32_t tmp = sA; sA = sB; sB = tmp;
    }

    // ---- epilogue: m16n8 C frag: c0,c1 @ (lane>>2, (lane&3)*2), c2,c3 @ row+8
    const int er = lane >> 2;
    const int ec = (lane & 3) * 2;
#pragma unroll
    for (int mi = 0; mi < 2; mi++) {
#pragma unroll
        for (int ni = 0; ni < NI; ni++) {
            const int row = m0 + warp_m * 32 + mi * 16 + er;
            const int col = n0 + warp_n * WT_N + ni * 8 + ec;
            float2 o0 = make_float2(acc[mi][ni][0] + bias[col], acc[mi][ni][1] + bias[col + 1]);
            float2 o1 = make_float2(acc[mi][ni][2] + bias[col], acc[mi][ni][3] + bias[col + 1]);
            *(float2*)&C[(size_t)row * ldc + col] = o0;
            *(float2*)&C[(size_t)(row + 8) * ldc + col] = o1;
        }
    }
}

// =====================================================================
// Operand prep
// =====================================================================
__device__ __forceinline__ void split2h(float v, __half& h, __half& l) {
    h = __float2half(v);
    l = __float2half(v - __half2float(h));
}

__global__ __launch_bounds__(256)
void split_x_kernel(const float* __restrict__ x) {
    const size_t i4 = ((size_t)blockIdx.x * 256 + threadIdx.x) * 4;
    float4 v = *(const float4*)(x + i4);
    __half h[4], l[4];
    split2h(v.x, h[0], l[0]); split2h(v.y, h[1], l[1]);
    split2h(v.z, h[2], l[2]); split2h(v.w, h[3], l[3]);
    *(uint2*)(g_Xh + i4) = *(uint2*)h;
    *(uint2*)(g_Xl + i4) = *(uint2*)l;
}

// transpose + round BOTH weights to fp16 in ONE launch.
__global__ __launch_bounds__(256)
void prep_w_all(const float* __restrict__ w_in, const float* __restrict__ w_out) {
    const int bx = blockIdx.x;
    const bool is1 = (bx < 64);
    const float* __restrict__ W = is1 ? w_in : w_out;
    __half* __restrict__ o = is1 ? g_W1 : g_W2;
    const int src_ld = is1 ? 3072 : 1024;
    const int n0 = (is1 ? bx : bx - 64) * 32;
    const int cbase = n0 + ((is1 && n0 >= 1024) ? 1024 : 0);
    const int k0 = blockIdx.y * 32;
    __shared__ float t[32][33];
    const int x = threadIdx.x, y = threadIdx.y;
#pragma unroll
    for (int j = 0; j < 4; j++)
        t[y + 8 * j][x] = W[(size_t)(k0 + y + 8 * j) * src_ld + cbase + x];
    __syncthreads();
#pragma unroll
    for (int j = 0; j < 4; j++)
        o[(size_t)(n0 + y + 8 * j) * 1024 + k0 + x] = __float2half(t[x][y + 8 * j]);
}

// =====================================================================
// Filter generation (row 0 only; t[0]==0 so w1 drops out) + bias gather
// =====================================================================
__device__ __forceinline__ float silu_f(float v) { return v / (1.f + __expf(-v)); }

__global__ void filtgen_kernel(const float* __restrict__ b1, const float* __restrict__ w2,
                               const float* __restrict__ b2, const float* __restrict__ w3,
                               const float* __restrict__ b_in) {
    __shared__ float m1[64], m2[64];
    __shared__ int flag;
    const int t = threadIdx.x;          // 1024 threads
    g_biasg[t] = b_in[t];
    g_biasg[t + 1024] = b_in[t + 2048];
    if (t == 0) flag = 0;
    if (t < 64) m1[t] = silu_f(b1[t]);
    __syncthreads();
    if (t < 64) {
        float a = b2[t];
#pragma unroll
        for (int i = 0; i < 64; i++) a += m1[i] * w2[i * 64 + t];
        m2[t] = silu_f(a);
    }
    __syncthreads();
    float a = 0.f;
#pragma unroll
    for (int j = 0; j < 64; j++) a += m2[j] * w3[j * 1024 + t];
    g_h[t] = a;
    if (a != 0.f) flag = 1;
    __syncthreads();
    if (t == 0) g_hnz = flag;
}

// =====================================================================
// FAST PATH (h == 0): fused depthwise conv + gate + pointwise "fir" +
// transpose-to-[m][k] + fp16 split, l-tiled with register rotation so
// g_U is read exactly once.  z = s0^2 * s2 * fb[d].
// =====================================================================
__global__ __launch_bounds__(256)
void fuse_fast_kernel(const float* __restrict__ wc, const float* __restrict__ bc,
                      const float* __restrict__ fb) {
    if (g_hnz != 0) return;
    const int l0 = blockIdx.x * 32, b = blockIdx.y;
    const int d4 = threadIdx.x * 4;
    const float* ub = g_U + ((size_t)(b * L_ + l0)) * NU_;
    const float4 zero = make_float4(0.f, 0.f, 0.f, 0.f);

    float c0t[3][4], c2t[3][4], b0v[4], b2v[4], fbv[4];
#pragma unroll
    for (int j = 0; j < 4; j++) {
        const int d = d4 + j, d2 = d + 2048;
        c0t[0][j] = wc[d * 3]; c0t[1][j] = wc[d * 3 + 1]; c0t[2][j] = wc[d * 3 + 2];
        c2t[0][j] = wc[d2 * 3]; c2t[1][j] = wc[d2 * 3 + 1]; c2t[2][j] = wc[d2 * 3 + 2];
        b0v[j] = bc[d]; b2v[j] = bc[d2]; fbv[j] = fb[d];
    }

    float4 u0a = (l0 >= 2) ? *(const float4*)(ub - 2 * NU_ + d4) : zero;
    float4 u2a = (l0 >= 2) ? *(const float4*)(ub - 2 * NU_ + 1024 + d4) : zero;
    float4 u0b = (l0 >= 1) ? *(const float4*)(ub - NU_ + d4) : zero;
    float4 u2b = (l0 >= 1) ? *(const float4*)(ub - NU_ + 1024 + d4) : zero;

#pragma unroll 4
    for (int i = 0; i < 32; i++) {
        float4 u0c = *(const float4*)(ub + (size_t)i * NU_ + d4);
        float4 u2c = *(const float4*)(ub + (size_t)i * NU_ + 1024 + d4);
        const float* p0a = &u0a.x; const float* p0b = &u0b.x; const float* p0c = &u0c.x;
        const float* p2a = &u2a.x; const float* p2b = &u2b.x; const float* p2c = &u2c.x;

        __half h[4], lo[4];
#pragma unroll
        for (int j = 0; j < 4; j++) {
            float s0 = c0t[0][j] * p0a[j] + c0t[1][j] * p0b[j] + c0t[2][j] * p0c[j] + b0v[j];
            float s2 = c2t[0][j] * p2a[j] + c2t[1][j] * p2b[j] + c2t[2][j] * p2c[j] + b2v[j];
            float z = s0 * s0 * s2 * fbv[j];
            split2h(z, h[j], lo[j]);
        }
        const size_t o = ((size_t)(b * L_ + l0 + i)) * 1024 + d4;
        *(uint2*)(g_Zth + o) = *(uint2*)h;
        *(uint2*)(g_Ztl + o) = *(uint2*)lo;

        u0a = u0b; u0b = u0c;
        u2a = u2b; u2b = u2c;
    }
}

// =====================================================================
// SLOW PATH (h != 0) — correctness fallback merged into ONE kernel.
// Inactive for this benchmark (h==0) — exits immediately.
// =====================================================================
__global__ __launch_bounds__(256)
void slow_path_kernel(const float* __restrict__ wc, const float* __restrict__ bc,
                      const float* __restrict__ fb) {
    if (g_hnz == 0) return;
    const int row = blockIdx.x;          // b*D + d
    const int b = row >> 10;
    const int d = row & (D_ - 1);
    const int d2 = d + 2048;
    const float c00 = wc[d * 3], c01 = wc[d * 3 + 1], c02 = wc[d * 3 + 2];
    const float c20 = wc[d2 * 3], c21 = wc[d2 * 3 + 1], c22 = wc[d2 * 3 + 2];
    const float b0v = bc[d], b2v = bc[d2], fbd = fb[d];

    __shared__ float hs[1024];
    __shared__ float s0s[4096];
    __shared__ float vs[1040 + 4096];    // 1040 leading zeros = causal padding

    for (int i = threadIdx.x; i < 1024; i += 256) hs[i] = g_h[i];
    for (int i = threadIdx.x; i < 1040; i += 256) vs[i] = 0.f;

    const float* Ub = g_U + (size_t)(b * L_) * NU_;
    for (int l = threadIdx.x; l < L_; l += 256) {
        float u0c = Ub[(size_t)l * NU_ + d];
        float u2c = Ub[(size_t)l * NU_ + 1024 + d];
        float u0b = (l >= 1) ? Ub[(size_t)(l - 1) * NU_ + d] : 0.f;
        float u2b = (l >= 1) ? Ub[(size_t)(l - 1) * NU_ + 1024 + d] : 0.f;
        float u0a = (l >= 2) ? Ub[(size_t)(l - 2) * NU_ + d] : 0.f;
        float u2a = (l >= 2) ? Ub[(size_t)(l - 2) * NU_ + 1024 + d] : 0.f;
        float s0 = c00 * u0a + c01 * u0b + c02 * u0c + b0v;
        float s2 = c20 * u2a + c21 * u2b + c22 * u2c + b2v;
        s0s[l] = s0;
        vs[1040 + l] = s0 * s2;
    }
    __syncthreads();

    const int l0 = threadIdx.x * 16;
    float acc[16];
#pragma unroll
    for (int i = 0; i < 16; i++) acc[i] = 0.f;
#pragma unroll 1
    for (int j0 = 0; j0 < 1024; j0 += 16) {
        float hh[16];
#pragma unroll
        for (int jj = 0; jj < 16; jj++) hh[jj] = hs[j0 + jj];
        float w[31];
        const int base = 1040 + l0 - j0 - 15;
#pragma unroll
        for (int k = 0; k < 31; k++) w[k] = vs[base + k];
#pragma unroll
        for (int i = 0; i < 16; i++)
#pragma unroll
            for (int jj = 0; jj < 16; jj++)
                acc[i] += hh[jj] * w[15 + i - jj];
    }
#pragma unroll
    for (int i = 0; i < 16; i++) {
        const int l = l0 + i;
        const float z = (acc[i] + vs[1040 + l] * fbd) * s0s[l];
        __half h, lo; split2h(z, h, lo);
        const size_t o = ((size_t)(b * L_ + l)) * 1024 + d;
        g_Zth[o] = h; g_Ztl[o] = lo;
    }
}

// =====================================================================
extern "C" void kernel_launch(void* const* d_in, const int* in_sizes, int n_in,
                              void* d_out, int out_size) {
    const float* x      = (const float*)d_in[0];
    const float* w_in   = (const float*)d_in[1];
    const float* b_in   = (const float*)d_in[2];
    const float* w_conv = (const float*)d_in[3];
    const float* b_conv = (const float*)d_in[4];
    // d_in[5] = w1 (multiplied by t[0]==0; unused for filters[0])
    const float* b1     = (const float*)d_in[6];
    const float* w2     = (const float*)d_in[7];
    const float* b2     = (const float*)d_in[8];
    const float* w3     = (const float*)d_in[9];
    const float* fbias  = (const float*)d_in[10];
    const float* w_out  = (const float*)d_in[11];
    const float* b_out  = (const float*)d_in[12];
    float* out = (float*)d_out;

    split_x_kernel<<<BL_ * D_ / 1024, 256>>>(x);
    prep_w_all<<<dim3(96, 32), dim3(32, 8)>>>(w_in, w_out);
    filtgen_kernel<<<1, 1024>>>(b1, w2, b2, w3, b_in);

    gemm_mma<0, 128><<<dim3(NU_ / 128, BL_ / 128), 256>>>(nullptr, nullptr);

    // slow path (no-op when h == 0)
    slow_path_kernel<<<B_ * D_, 256>>>(w_conv, b_conv, fbias);
    // fast path (no-op when h != 0)
    fuse_fast_kernel<<<dim3(L_ / 32, B_), 256>>>(w_conv, b_conv, fbias);

    gemm_mma<1, 64><<<dim3(1024 / 128, BL_ / 64), 256>>>(b_out, out);
}

// round 14
// speedup vs baseline: 1.1457x; 1.1230x over previous
#include <cuda_runtime.h>
#include <cuda_fp16.h>
#include <cstdint>

#define B_  2
#define L_  4096
#define D_  1024
#define BL_ 8192        // B_*L_
#define NU_ 2048        // kept columns of GEMM1 (stream0 + stream2)

// ---------------- scratch (static device globals; no allocation) ----------------
__device__ float g_U [(size_t)BL_ * NU_];        // GEMM1 out: [b*L+l][2048] fp32
__device__ float g_h [D_];
__device__ int   g_hnz;
__device__ __half g_Xh [(size_t)BL_ * D_];   // x split hi (fp16)
__device__ __half g_Xl [(size_t)BL_ * D_];   // x split lo
__device__ __half g_Zth[(size_t)BL_ * D_];   // z (as [m][k]) fp16 (single precision operand)
__device__ __half g_W1 [(size_t)NU_ * D_];   // w_in kept cols, [n][k], single fp16
__device__ __half g_W2 [(size_t)D_ * D_];    // w_out, [n][k], single fp16
__device__ float g_biasg[NU_];

// ---------------- PTX helpers (arch-generic: sm_80+ features only) ----------------
__device__ __forceinline__ uint32_t smem_u32(const void* p) {
    uint32_t a;
    asm("{ .reg .u64 t; cvta.to.shared.u64 t, %1; cvt.u32.u64 %0, t; }" : "=r"(a) : "l"(p));
    return a;
}
__device__ __forceinline__ uint32_t swz(uint32_t o) { return o ^ ((o >> 3) & 0x70); }
__device__ __forceinline__ void cp16(uint32_t s, const void* g) {
    asm volatile("cp.async.cg.shared.global [%0], [%1], 16;" :: "r"(s), "l"(g));
}
__device__ __forceinline__ void cp_commit() {
    asm volatile("cp.async.commit_group;");
}
template <int N>
__device__ __forceinline__ void cp_wait() {
    asm volatile("cp.async.wait_group %0;" :: "n"(N));
}
__device__ __forceinline__ void ldsm4(uint32_t& r0, uint32_t& r1, uint32_t& r2, uint32_t& r3,
                                      uint32_t addr) {
    asm volatile("ldmatrix.sync.aligned.m8n8.x4.shared.b16 {%0,%1,%2,%3}, [%4];"
                 : "=r"(r0), "=r"(r1), "=r"(r2), "=r"(r3) : "r"(addr));
}
__device__ __forceinline__ void mma16816(float& c0, float& c1, float& c2, float& c3,
                                         uint32_t a0, uint32_t a1, uint32_t a2, uint32_t a3,
                                         uint32_t b0, uint32_t b1) {
    asm volatile("mma.sync.aligned.m16n8k16.row.col.f32.f16.f16.f32 "
                 "{%0,%1,%2,%3}, {%4,%5,%6,%7}, {%8,%9}, {%0,%1,%2,%3};"
                 : "+f"(c0), "+f"(c1), "+f"(c2), "+f"(c3)
                 : "r"(a0), "r"(a1), "r"(a2), "r"(a3), "r"(b0), "r"(b1));
}

// =====================================================================
// fp16 GEMM via ldmatrix + mma.sync (HMMA).
//   SPLIT=1: C = Ah*B + Al*B  (A exact via hi/lo split; error = B rounding)
//   SPLIT=0: C = A*B          (single-pass; adds ~2^-11 A-rounding error)
// BK=64 chunks (16 iters), SW128 XOR-swizzled smem, 2 stages, one
// __syncthreads per chunk, depth-1 prefetch.  Interleaved fragment order
// (measured best; upfront hoist regressed from register pressure).
// TM=128: 8 warps 4(m)x2(n), warp tile 32x64, 2 CTAs/SM.
// TM=64 : 8 warps 2(m)x4(n), warp tile 32x32, 3 CTAs/SM.
// WHICH=0: GEMM1 (Xh/Xl x W1 -> g_U, bias g_biasg, ldc 2048)  SPLIT=1
// WHICH=1: GEMM2 (Zth  x W2 -> out, bias param,  ldc 1024)    SPLIT=0
// =====================================================================
template <int WHICH, int TM, int SPLIT>
__global__ __launch_bounds__(256, TM == 128 ? 2 : 3)
void gemm_mma(const float* __restrict__ bias_p, float* __restrict__ C_p) {
    constexpr int WM_CNT = (TM == 128) ? 4 : 2;     // warps along M
    constexpr int WT_N   = 128 / (8 / WM_CNT);      // warp tile N (64 or 32)
    constexpr int NI     = WT_N / 8;                // n-frags per warp (8 or 4)
    constexpr int NA     = SPLIT ? 2 : 1;           // A tiles per stage
    constexpr int ATILE_B = TM * 128;               // bytes per A tile
    constexpr int BTILE_B = 16384;                  // 128x64 fp16
    constexpr int STAGE_H = (NA * ATILE_B + BTILE_B) / 2;

    __shared__ __align__(1024) __half sm[2][STAGE_H];   // A(h[,l])|B per stage

    const int tid = threadIdx.x;
    const int lane = tid & 31;
    const int wid = tid >> 5;
    const int warp_m = wid % WM_CNT;
    const int warp_n = wid / WM_CNT;
    const int m0 = blockIdx.y * TM;
    const int n0 = blockIdx.x * 128;

    const __half* __restrict__ Ah = WHICH ? g_Zth : g_Xh;
    const __half* __restrict__ Al = WHICH ? g_Zth : g_Xl;   // unused when !SPLIT
    const __half* __restrict__ Bw = WHICH ? g_W2 : g_W1;
    const float* __restrict__ bias = WHICH ? bias_p : g_biasg;
    float* __restrict__ C = WHICH ? C_p : g_U;
    const int ldc = WHICH ? 1024 : 2048;

    const __half* gpA[2] = {Ah, Al};

    uint32_t sA = smem_u32(sm[0]);      // compute stage
    uint32_t sB = smem_u32(sm[1]);      // prefetch stage

    float acc[2][NI][4];
#pragma unroll
    for (int i = 0; i < 2; i++)
#pragma unroll
        for (int j = 0; j < NI; j++)
#pragma unroll
            for (int q = 0; q < 4; q++) acc[i][j][q] = 0.f;

    // ldmatrix lane->local-row maps
    const int a_loc = (lane & 7) + ((lane >> 3) & 1) * 8;   // m0k0,m8k0,m0k8,m8k8
    const int a_kb  = (lane >> 4) * 16;                     // bytes
    const int b_loc = (lane & 7) + ((lane >> 4) & 1) * 8;   // n0k0,n0k8,n8k0,n8k8
    const int b_kb  = ((lane >> 3) & 1) * 16;               // bytes

    auto load_chunk = [&](uint32_t dst, int k0) {
#pragma unroll
        for (int t = 0; t < NA; t++) {                      // A tiles (TM rows)
#pragma unroll
            for (int j = 0; j < TM / 32; j++) {
                const int id = tid + j * 256;
                const int row = id >> 3, seg = id & 7;
                cp16(dst + t * ATILE_B + swz(row * 128 + seg * 16),
                     gpA[t] + (size_t)(m0 + row) * 1024 + k0 + seg * 8);
            }
        }
#pragma unroll
        for (int j = 0; j < 4; j++) {                       // B tile (128 rows)
            const int id = tid + j * 256;
            const int row = id >> 3, seg = id & 7;
            cp16(dst + NA * ATILE_B + swz(row * 128 + seg * 16),
                 Bw + (size_t)(n0 + row) * 1024 + k0 + seg * 8);
        }
        cp_commit();
    };

    load_chunk(sA, 0);

#pragma unroll 1
    for (int kc = 0; kc < 16; kc++) {
        cp_wait<0>();
        __syncthreads();                 // publish chunk kc; anti-WAR for sB

        if (kc + 1 < 16) load_chunk(sB, (kc + 1) * 64);

#pragma unroll
        for (int kk = 0; kk < 4; kk++) {
            const uint32_t kbase = kk * 32;           // bytes within 128B row
            // B fragments (shared by both passes)
            uint32_t bh[NI][2];
#pragma unroll
            for (int nj = 0; nj < NI / 2; nj++) {
                uint32_t r0, r1, r2, r3;
                ldsm4(r0, r1, r2, r3, sA + NA * ATILE_B
                      + swz((warp_n * WT_N + nj * 16 + b_loc) * 128 + kbase + b_kb));
                bh[nj * 2 + 0][0] = r0; bh[nj * 2 + 0][1] = r1;
                bh[nj * 2 + 1][0] = r2; bh[nj * 2 + 1][1] = r3;
            }
            // A hi fragments -> MMA
            uint32_t a[2][4];
#pragma unroll
            for (int mi = 0; mi < 2; mi++)
                ldsm4(a[mi][0], a[mi][1], a[mi][2], a[mi][3],
                      sA + swz((warp_m * 32 + mi * 16 + a_loc) * 128 + kbase + a_kb));
#pragma unroll
            for (int mi = 0; mi < 2; mi++)
#pragma unroll
                for (int ni = 0; ni < NI; ni++)
                    mma16816(acc[mi][ni][0], acc[mi][ni][1], acc[mi][ni][2], acc[mi][ni][3],
                             a[mi][0], a[mi][1], a[mi][2], a[mi][3], bh[ni][0], bh[ni][1]);
            if (SPLIT) {
                // A lo fragments -> MMA (reuse regs)
#pragma unroll
                for (int mi = 0; mi < 2; mi++)
                    ldsm4(a[mi][0], a[mi][1], a[mi][2], a[mi][3],
                          sA + ATILE_B + swz((warp_m * 32 + mi * 16 + a_loc) * 128 + kbase + a_kb));
#pragma unroll
                for (int mi = 0; mi < 2; mi++)
#pragma unroll
                    for (int ni = 0; ni < NI; ni++)
                        mma16816(acc[mi][ni][0], acc[mi][ni][1], acc[mi][ni][2], acc[mi][ni][3],
                                 a[mi][0], a[mi][1], a[mi][2], a[mi][3], bh[ni][0], bh[ni][1]);
            }
        }
        const uint32_t tmp = sA; sA = sB; sB = tmp;
    }

    // ---- epilogue: m16n8 C frag: c0,c1 @ (lane>>2, (lane&3)*2), c2,c3 @ row+8
    const int er = lane >> 2;
    const int ec = (lane & 3) * 2;
#pragma unroll
    for (int mi = 0; mi < 2; mi++) {
#pragma unroll
        for (int ni = 0; ni < NI; ni++) {
            const int row = m0 + warp_m * 32 + mi * 16 + er;
            const int col = n0 + warp_n * WT_N + ni * 8 + ec;
            float2 o0 = make_float2(acc[mi][ni][0] + bias[col], acc[mi][ni][1] + bias[col + 1]);
            float2 o1 = make_float2(acc[mi][ni][2] + bias[col], acc[mi][ni][3] + bias[col + 1]);
            *(float2*)&C[(size_t)row * ldc + col] = o0;
            *(float2*)&C[(size_t)(row + 8) * ldc + col] = o1;
        }
    }
}

// =====================================================================
// Operand prep
// =====================================================================
__device__ __forceinline__ void split2h(float v, __half& h, __half& l) {
    h = __float2half(v);
    l = __float2half(v - __half2float(h));
}

__global__ __launch_bounds__(256)
void split_x_kernel(const float* __restrict__ x) {
    const size_t i4 = ((size_t)blockIdx.x * 256 + threadIdx.x) * 4;
    float4 v = *(const float4*)(x + i4);
    __half h[4], l[4];
    split2h(v.x, h[0], l[0]); split2h(v.y, h[1], l[1]);
    split2h(v.z, h[2], l[2]); split2h(v.w, h[3], l[3]);
    *(uint2*)(g_Xh + i4) = *(uint2*)h;
    *(uint2*)(g_Xl + i4) = *(uint2*)l;
}

// transpose + round BOTH weights to fp16 in ONE launch.
__global__ __launch_bounds__(256)
void prep_w_all(const float* __restrict__ w_in, const float* __restrict__ w_out) {
    const int bx = blockIdx.x;
    const bool is1 = (bx < 64);
    const float* __restrict__ W = is1 ? w_in : w_out;
    __half* __restrict__ o = is1 ? g_W1 : g_W2;
    const int src_ld = is1 ? 3072 : 1024;
    const int n0 = (is1 ? bx : bx - 64) * 32;
    const int cbase = n0 + ((is1 && n0 >= 1024) ? 1024 : 0);
    const int k0 = blockIdx.y * 32;
    __shared__ float t[32][33];
    const int x = threadIdx.x, y = threadIdx.y;
#pragma unroll
    for (int j = 0; j < 4; j++)
        t[y + 8 * j][x] = W[(size_t)(k0 + y + 8 * j) * src_ld + cbase + x];
    __syncthreads();
#pragma unroll
    for (int j = 0; j < 4; j++)
        o[(size_t)(n0 + y + 8 * j) * 1024 + k0 + x] = __float2half(t[x][y + 8 * j]);
}

// =====================================================================
// Filter generation (row 0 only; t[0]==0 so w1 drops out) + bias gather
// =====================================================================
__device__ __forceinline__ float silu_f(float v) { return v / (1.f + __expf(-v)); }

__global__ void filtgen_kernel(const float* __restrict__ b1, const float* __restrict__ w2,
                               const float* __restrict__ b2, const float* __restrict__ w3,
                               const float* __restrict__ b_in) {
    __shared__ float m1[64], m2[64];
    __shared__ int flag;
    const int t = threadIdx.x;          // 1024 threads
    g_biasg[t] = b_in[t];
    g_biasg[t + 1024] = b_in[t + 2048];
    if (t == 0) flag = 0;
    if (t < 64) m1[t] = silu_f(b1[t]);
    __syncthreads();
    if (t < 64) {
        float a = b2[t];
#pragma unroll
        for (int i = 0; i < 64; i++) a += m1[i] * w2[i * 64 + t];
        m2[t] = silu_f(a);
    }
    __syncthreads();
    float a = 0.f;
#pragma unroll
    for (int j = 0; j < 64; j++) a += m2[j] * w3[j * 1024 + t];
    g_h[t] = a;
    if (a != 0.f) flag = 1;
    __syncthreads();
    if (t == 0) g_hnz = flag;
}

// =====================================================================
// FAST PATH (h == 0): fused depthwise conv + gate + pointwise "fir" +
// transpose-to-[m][k] + fp16 round, l-tiled with register rotation so
// g_U is read exactly once.  z = s0^2 * s2 * fb[d].
// =====================================================================
__global__ __launch_bounds__(256)
void fuse_fast_kernel(const float* __restrict__ wc, const float* __restrict__ bc,
                      const float* __restrict__ fb) {
    if (g_hnz != 0) return;
    const int l0 = blockIdx.x * 32, b = blockIdx.y;
    const int d4 = threadIdx.x * 4;
    const float* ub = g_U + ((size_t)(b * L_ + l0)) * NU_;
    const float4 zero = make_float4(0.f, 0.f, 0.f, 0.f);

    float c0t[3][4], c2t[3][4], b0v[4], b2v[4], fbv[4];
#pragma unroll
    for (int j = 0; j < 4; j++) {
        const int d = d4 + j, d2 = d + 2048;
        c0t[0][j] = wc[d * 3]; c0t[1][j] = wc[d * 3 + 1]; c0t[2][j] = wc[d * 3 + 2];
        c2t[0][j] = wc[d2 * 3]; c2t[1][j] = wc[d2 * 3 + 1]; c2t[2][j] = wc[d2 * 3 + 2];
        b0v[j] = bc[d]; b2v[j] = bc[d2]; fbv[j] = fb[d];
    }

    float4 u0a = (l0 >= 2) ? *(const float4*)(ub - 2 * NU_ + d4) : zero;
    float4 u2a = (l0 >= 2) ? *(const float4*)(ub - 2 * NU_ + 1024 + d4) : zero;
    float4 u0b = (l0 >= 1) ? *(const float4*)(ub - NU_ + d4) : zero;
    float4 u2b = (l0 >= 1) ? *(const float4*)(ub - NU_ + 1024 + d4) : zero;

#pragma unroll 4
    for (int i = 0; i < 32; i++) {
        float4 u0c = *(const float4*)(ub + (size_t)i * NU_ + d4);
        float4 u2c = *(const float4*)(ub + (size_t)i * NU_ + 1024 + d4);
        const float* p0a = &u0a.x; const float* p0b = &u0b.x; const float* p0c = &u0c.x;
        const float* p2a = &u2a.x; const float* p2b = &u2b.x; const float* p2c = &u2c.x;

        __half h[4];
#pragma unroll
        for (int j = 0; j < 4; j++) {
            float s0 = c0t[0][j] * p0a[j] + c0t[1][j] * p0b[j] + c0t[2][j] * p0c[j] + b0v[j];
            float s2 = c2t[0][j] * p2a[j] + c2t[1][j] * p2b[j] + c2t[2][j] * p2c[j] + b2v[j];
            float z = s0 * s0 * s2 * fbv[j];
            h[j] = __float2half(z);
        }
        const size_t o = ((size_t)(b * L_ + l0 + i)) * 1024 + d4;
        *(uint2*)(g_Zth + o) = *(uint2*)h;

        u0a = u0b; u0b = u0c;
        u2a = u2b; u2b = u2c;
    }
}

// =====================================================================
// SLOW PATH (h != 0) — correctness fallback merged into ONE kernel.
// Inactive for this benchmark (h==0) — exits immediately.
// =====================================================================
__global__ __launch_bounds__(256)
void slow_path_kernel(const float* __restrict__ wc, const float* __restrict__ bc,
                      const float* __restrict__ fb) {
    if (g_hnz == 0) return;
    const int row = blockIdx.x;          // b*D + d
    const int b = row >> 10;
    const int d = row & (D_ - 1);
    const int d2 = d + 2048;
    const float c00 = wc[d * 3], c01 = wc[d * 3 + 1], c02 = wc[d * 3 + 2];
    const float c20 = wc[d2 * 3], c21 = wc[d2 * 3 + 1], c22 = wc[d2 * 3 + 2];
    const float b0v = bc[d], b2v = bc[d2], fbd = fb[d];

    __shared__ float hs[1024];
    __shared__ float s0s[4096];
    __shared__ float vs[1040 + 4096];    // 1040 leading zeros = causal padding

    for (int i = threadIdx.x; i < 1024; i += 256) hs[i] = g_h[i];
    for (int i = threadIdx.x; i < 1040; i += 256) vs[i] = 0.f;

    const float* Ub = g_U + (size_t)(b * L_) * NU_;
    for (int l = threadIdx.x; l < L_; l += 256) {
        float u0c = Ub[(size_t)l * NU_ + d];
        float u2c = Ub[(size_t)l * NU_ + 1024 + d];
        float u0b = (l >= 1) ? Ub[(size_t)(l - 1) * NU_ + d] : 0.f;
        float u2b = (l >= 1) ? Ub[(size_t)(l - 1) * NU_ + 1024 + d] : 0.f;
        float u0a = (l >= 2) ? Ub[(size_t)(l - 2) * NU_ + d] : 0.f;
        float u2a = (l >= 2) ? Ub[(size_t)(l - 2) * NU_ + 1024 + d] : 0.f;
        float s0 = c00 * u0a + c01 * u0b + c02 * u0c + b0v;
        float s2 = c20 * u2a + c21 * u2b + c22 * u2c + b2v;
        s0s[l] = s0;
        vs[1040 + l] = s0 * s2;
    }
    __syncthreads();

    const int l0 = threadIdx.x * 16;
    float acc[16];
#pragma unroll
    for (int i = 0; i < 16; i++) acc[i] = 0.f;
#pragma unroll 1
    for (int j0 = 0; j0 < 1024; j0 += 16) {
        float hh[16];
#pragma unroll
        for (int jj = 0; jj < 16; jj++) hh[jj] = hs[j0 + jj];
        float w[31];
        const int base = 1040 + l0 - j0 - 15;
#pragma unroll
        for (int k = 0; k < 31; k++) w[k] = vs[base + k];
#pragma unroll
        for (int i = 0; i < 16; i++)
#pragma unroll
            for (int jj = 0; jj < 16; jj++)
                acc[i] += hh[jj] * w[15 + i - jj];
    }
#pragma unroll
    for (int i = 0; i < 16; i++) {
        const int l = l0 + i;
        const float z = (acc[i] + vs[1040 + l] * fbd) * s0s[l];
        g_Zth[((size_t)(b * L_ + l)) * 1024 + d] = __float2half(z);
    }
}

// =====================================================================
extern "C" void kernel_launch(void* const* d_in, const int* in_sizes, int n_in,
                              void* d_out, int out_size) {
    const float* x      = (const float*)d_in[0];
    const float* w_in   = (const float*)d_in[1];
    const float* b_in   = (const float*)d_in[2];
    const float* w_conv = (const float*)d_in[3];
    const float* b_conv = (const float*)d_in[4];
    // d_in[5] = w1 (multiplied by t[0]==0; unused for filters[0])
    const float* b1     = (const float*)d_in[6];
    const float* w2     = (const float*)d_in[7];
    const float* b2     = (const float*)d_in[8];
    const float* w3     = (const float*)d_in[9];
    const float* fbias  = (const float*)d_in[10];
    const float* w_out  = (const float*)d_in[11];
    const float* b_out  = (const float*)d_in[12];
    float* out = (float*)d_out;

    split_x_kernel<<<BL_ * D_ / 1024, 256>>>(x);
    prep_w_all<<<dim3(96, 32), dim3(32, 8)>>>(w_in, w_out);
    filtgen_kernel<<<1, 1024>>>(b1, w2, b2, w3, b_in);

    gemm_mma<0, 128, 1><<<dim3(NU_ / 128, BL_ / 128), 256>>>(nullptr, nullptr);

    // slow path (no-op when h == 0)
    slow_path_kernel<<<B_ * D_, 256>>>(w_conv, b_conv, fbias);
    // fast path (no-op when h != 0)
    fuse_fast_kernel<<<dim3(L_ / 32, B_), 256>>>(w_conv, b_conv, fbias);

    gemm_mma<1, 64, 0><<<dim3(1024 / 128, BL_ / 64), 256>>>(b_out, out);
}

// round 15
// speedup vs baseline: 1.5311x; 1.3364x over previous
#include <cuda_runtime.h>
#include <cuda_fp16.h>
#include <cstdint>

#define B_  2
#define L_  4096
#define D_  1024
#define BL_ 8192        // B_*L_
#define NU_ 2048        // kept columns of GEMM1 (stream0 + stream2)

// ---------------- scratch (static device globals; no allocation) ----------------
__device__ float g_U [(size_t)BL_ * NU_];        // GEMM1 out: [b*L+l][2048] fp32
__device__ float g_h [D_];
__device__ int   g_hnz;
__device__ __half g_Xh [(size_t)BL_ * D_];   // x rounded to fp16
__device__ __half g_Zth[(size_t)BL_ * D_];   // z (as [m][k]) fp16
__device__ __half g_W1 [(size_t)NU_ * D_];   // w_in kept cols, [n][k], fp16
__device__ __half g_W2 [(size_t)D_ * D_];    // w_out, [n][k], fp16
__device__ float g_biasg[NU_];

// ---------------- PTX helpers (arch-generic: sm_80+ features only) ----------------
__device__ __forceinline__ uint32_t smem_u32(const void* p) {
    uint32_t a;
    asm("{ .reg .u64 t; cvta.to.shared.u64 t, %1; cvt.u32.u64 %0, t; }" : "=r"(a) : "l"(p));
    return a;
}
__device__ __forceinline__ uint32_t swz(uint32_t o) { return o ^ ((o >> 3) & 0x70); }
__device__ __forceinline__ void cp16(uint32_t s, const void* g) {
    asm volatile("cp.async.cg.shared.global [%0], [%1], 16;" :: "r"(s), "l"(g));
}
__device__ __forceinline__ void cp_commit() {
    asm volatile("cp.async.commit_group;");
}
template <int N>
__device__ __forceinline__ void cp_wait() {
    asm volatile("cp.async.wait_group %0;" :: "n"(N));
}
__device__ __forceinline__ void ldsm4(uint32_t& r0, uint32_t& r1, uint32_t& r2, uint32_t& r3,
                                      uint32_t addr) {
    asm volatile("ldmatrix.sync.aligned.m8n8.x4.shared.b16 {%0,%1,%2,%3}, [%4];"
                 : "=r"(r0), "=r"(r1), "=r"(r2), "=r"(r3) : "r"(addr));
}
__device__ __forceinline__ void mma16816(float& c0, float& c1, float& c2, float& c3,
                                         uint32_t a0, uint32_t a1, uint32_t a2, uint32_t a3,
                                         uint32_t b0, uint32_t b1) {
    asm volatile("mma.sync.aligned.m16n8k16.row.col.f32.f16.f16.f32 "
                 "{%0,%1,%2,%3}, {%4,%5,%6,%7}, {%8,%9}, {%0,%1,%2,%3};"
                 : "+f"(c0), "+f"(c1), "+f"(c2), "+f"(c3)
                 : "r"(a0), "r"(a1), "r"(a2), "r"(a3), "r"(b0), "r"(b1));
}

// =====================================================================
// fp16 single-pass GEMM via ldmatrix + mma.sync (HMMA).
//   C = A*B (+bias), A and B both rounded to fp16 (error budget audited:
//   total output rel_err ~5.3e-4 < 1e-3 with ~1.9x margin).
// BK=64 chunks (16 iters), SW128 XOR-swizzled smem, 2 stages, one
// __syncthreads per chunk, depth-1 prefetch.  Interleaved fragment order.
// TM=128: 8 warps 4(m)x2(n), warp tile 32x64, 2 CTAs/SM  (GEMM1).
// TM=64 : 8 warps 2(m)x4(n), warp tile 32x32, 3 CTAs/SM  (GEMM2).
// WHICH=0: GEMM1 (Xh x W1 -> g_U, bias g_biasg, ldc 2048)
// WHICH=1: GEMM2 (Zth x W2 -> out, bias param, ldc 1024)
// =====================================================================
template <int WHICH, int TM>
__global__ __launch_bounds__(256, TM == 128 ? 2 : 3)
void gemm_mma(const float* __restrict__ bias_p, float* __restrict__ C_p) {
    constexpr int WM_CNT = (TM == 128) ? 4 : 2;     // warps along M
    constexpr int WT_N   = 128 / (8 / WM_CNT);      // warp tile N (64 or 32)
    constexpr int NI     = WT_N / 8;                // n-frags per warp (8 or 4)
    constexpr int ATILE_B = TM * 128;               // bytes per A tile
    constexpr int BTILE_B = 16384;                  // 128x64 fp16
    constexpr int STAGE_H = (ATILE_B + BTILE_B) / 2;

    __shared__ __align__(1024) __half sm[2][STAGE_H];   // A|B per stage

    const int tid = threadIdx.x;
    const int lane = tid & 31;
    const int wid = tid >> 5;
    const int warp_m = wid % WM_CNT;
    const int warp_n = wid / WM_CNT;
    const int m0 = blockIdx.y * TM;
    const int n0 = blockIdx.x * 128;

    const __half* __restrict__ Ag = WHICH ? g_Zth : g_Xh;
    const __half* __restrict__ Bw = WHICH ? g_W2 : g_W1;
    const float* __restrict__ bias = WHICH ? bias_p : g_biasg;
    float* __restrict__ C = WHICH ? C_p : g_U;
    const int ldc = WHICH ? 1024 : 2048;

    uint32_t sA = smem_u32(sm[0]);      // compute stage
    uint32_t sB = smem_u32(sm[1]);      // prefetch stage

    float acc[2][NI][4];
#pragma unroll
    for (int i = 0; i < 2; i++)
#pragma unroll
        for (int j = 0; j < NI; j++)
#pragma unroll
            for (int q = 0; q < 4; q++) acc[i][j][q] = 0.f;

    // ldmatrix lane->local-row maps
    const int a_loc = (lane & 7) + ((lane >> 3) & 1) * 8;   // m0k0,m8k0,m0k8,m8k8
    const int a_kb  = (lane >> 4) * 16;                     // bytes
    const int b_loc = (lane & 7) + ((lane >> 4) & 1) * 8;   // n0k0,n0k8,n8k0,n8k8
    const int b_kb  = ((lane >> 3) & 1) * 16;               // bytes

    auto load_chunk = [&](uint32_t dst, int k0) {
#pragma unroll
        for (int j = 0; j < TM / 32; j++) {                 // A tile (TM rows)
            const int id = tid + j * 256;
            const int row = id >> 3, seg = id & 7;
            cp16(dst + swz(row * 128 + seg * 16),
                 Ag + (size_t)(m0 + row) * 1024 + k0 + seg * 8);
        }
#pragma unroll
        for (int j = 0; j < 4; j++) {                       // B tile (128 rows)
            const int id = tid + j * 256;
            const int row = id >> 3, seg = id & 7;
            cp16(dst + ATILE_B + swz(row * 128 + seg * 16),
                 Bw + (size_t)(n0 + row) * 1024 + k0 + seg * 8);
        }
        cp_commit();
    };

    load_chunk(sA, 0);

#pragma unroll 1
    for (int kc = 0; kc < 16; kc++) {
        cp_wait<0>();
        __syncthreads();                 // publish chunk kc; anti-WAR for sB

        if (kc + 1 < 16) load_chunk(sB, (kc + 1) * 64);

#pragma unroll
        for (int kk = 0; kk < 4; kk++) {
            const uint32_t kbase = kk * 32;           // bytes within 128B row
            uint32_t bh[NI][2];
#pragma unroll
            for (int nj = 0; nj < NI / 2; nj++) {
                uint32_t r0, r1, r2, r3;
                ldsm4(r0, r1, r2, r3, sA + ATILE_B
                      + swz((warp_n * WT_N + nj * 16 + b_loc) * 128 + kbase + b_kb));
                bh[nj * 2 + 0][0] = r0; bh[nj * 2 + 0][1] = r1;
                bh[nj * 2 + 1][0] = r2; bh[nj * 2 + 1][1] = r3;
            }
            uint32_t a[2][4];
#pragma unroll
            for (int mi = 0; mi < 2; mi++)
                ldsm4(a[mi][0], a[mi][1], a[mi][2], a[mi][3],
                      sA + swz((warp_m * 32 + mi * 16 + a_loc) * 128 + kbase + a_kb));
#pragma unroll
            for (int mi = 0; mi < 2; mi++)
#pragma unroll
                for (int ni = 0; ni < NI; ni++)
                    mma16816(acc[mi][ni][0], acc[mi][ni][1], acc[mi][ni][2], acc[mi][ni][3],
                             a[mi][0], a[mi][1], a[mi][2], a[mi][3], bh[ni][0], bh[ni][1]);
        }
        const uint32_t tmp = sA; sA = sB; sB = tmp;
    }

    // ---- epilogue: m16n8 C frag: c0,c1 @ (lane>>2, (lane&3)*2), c2,c3 @ row+8
    const int er = lane >> 2;
    const int ec = (lane & 3) * 2;
#pragma unroll
    for (int mi = 0; mi < 2; mi++) {
#pragma unroll
        for (int ni = 0; ni < NI; ni++) {
            const int row = m0 + warp_m * 32 + mi * 16 + er;
            const int col = n0 + warp_n * WT_N + ni * 8 + ec;
            float2 o0 = make_float2(acc[mi][ni][0] + bias[col], acc[mi][ni][1] + bias[col + 1]);
            float2 o1 = make_float2(acc[mi][ni][2] + bias[col], acc[mi][ni][3] + bias[col + 1]);
            *(float2*)&C[(size_t)row * ldc + col] = o0;
            *(float2*)&C[(size_t)(row + 8) * ldc + col] = o1;
        }
    }
}

// =====================================================================
// Operand prep
// =====================================================================
__global__ __launch_bounds__(256)
void split_x_kernel(const float* __restrict__ x) {
    const size_t i4 = ((size_t)blockIdx.x * 256 + threadIdx.x) * 4;
    float4 v = *(const float4*)(x + i4);
    __half h[4];
    h[0] = __float2half(v.x); h[1] = __float2half(v.y);
    h[2] = __float2half(v.z); h[3] = __float2half(v.w);
    *(uint2*)(g_Xh + i4) = *(uint2*)h;
}

// transpose + round BOTH weights to fp16 in ONE launch.
__global__ __launch_bounds__(256)
void prep_w_all(const float* __restrict__ w_in, const float* __restrict__ w_out) {
    const int bx = blockIdx.x;
    const bool is1 = (bx < 64);
    const float* __restrict__ W = is1 ? w_in : w_out;
    __half* __restrict__ o = is1 ? g_W1 : g_W2;
    const int src_ld = is1 ? 3072 : 1024;
    const int n0 = (is1 ? bx : bx - 64) * 32;
    const int cbase = n0 + ((is1 && n0 >= 1024) ? 1024 : 0);
    const int k0 = blockIdx.y * 32;
    __shared__ float t[32][33];
    const int x = threadIdx.x, y = threadIdx.y;
#pragma unroll
    for (int j = 0; j < 4; j++)
        t[y + 8 * j][x] = W[(size_t)(k0 + y + 8 * j) * src_ld + cbase + x];
    __syncthreads();
#pragma unroll
    for (int j = 0; j < 4; j++)
        o[(size_t)(n0 + y + 8 * j) * 1024 + k0 + x] = __float2half(t[x][y + 8 * j]);
}

// =====================================================================
// Filter generation (row 0 only; t[0]==0 so w1 drops out) + bias gather
// =====================================================================
__device__ __forceinline__ float silu_f(float v) { return v / (1.f + __expf(-v)); }

__global__ void filtgen_kernel(const float* __restrict__ b1, const float* __restrict__ w2,
                               const float* __restrict__ b2, const float* __restrict__ w3,
                               const float* __restrict__ b_in) {
    __shared__ float m1[64], m2[64];
    __shared__ int flag;
    const int t = threadIdx.x;          // 1024 threads
    g_biasg[t] = b_in[t];
    g_biasg[t + 1024] = b_in[t + 2048];
    if (t == 0) flag = 0;
    if (t < 64) m1[t] = silu_f(b1[t]);
    __syncthreads();
    if (t < 64) {
        float a = b2[t];
#pragma unroll
        for (int i = 0; i < 64; i++) a += m1[i] * w2[i * 64 + t];
        m2[t] = silu_f(a);
    }
    __syncthreads();
    float a = 0.f;
#pragma unroll
    for (int j = 0; j < 64; j++) a += m2[j] * w3[j * 1024 + t];
    g_h[t] = a;
    if (a != 0.f) flag = 1;
    __syncthreads();
    if (t == 0) g_hnz = flag;
}

// =====================================================================
// FAST PATH (h == 0): fused depthwise conv + gate + pointwise "fir" +
// transpose-to-[m][k] + fp16 round, l-tiled with register rotation so
// g_U is read exactly once.  z = s0^2 * s2 * fb[d].
// =====================================================================
__global__ __launch_bounds__(256)
void fuse_fast_kernel(const float* __restrict__ wc, const float* __restrict__ bc,
                      const float* __restrict__ fb) {
    if (g_hnz != 0) return;
    const int l0 = blockIdx.x * 32, b = blockIdx.y;
    const int d4 = threadIdx.x * 4;
    const float* ub = g_U + ((size_t)(b * L_ + l0)) * NU_;
    const float4 zero = make_float4(0.f, 0.f, 0.f, 0.f);

    float c0t[3][4], c2t[3][4], b0v[4], b2v[4], fbv[4];
#pragma unroll
    for (int j = 0; j < 4; j++) {
        const int d = d4 + j, d2 = d + 2048;
        c0t[0][j] = wc[d * 3]; c0t[1][j] = wc[d * 3 + 1]; c0t[2][j] = wc[d * 3 + 2];
        c2t[0][j] = wc[d2 * 3]; c2t[1][j] = wc[d2 * 3 + 1]; c2t[2][j] = wc[d2 * 3 + 2];
        b0v[j] = bc[d]; b2v[j] = bc[d2]; fbv[j] = fb[d];
    }

    float4 u0a = (l0 >= 2) ? *(const float4*)(ub - 2 * NU_ + d4) : zero;
    float4 u2a = (l0 >= 2) ? *(const float4*)(ub - 2 * NU_ + 1024 + d4) : zero;
    float4 u0b = (l0 >= 1) ? *(const float4*)(ub - NU_ + d4) : zero;
    float4 u2b = (l0 >= 1) ? *(const float4*)(ub - NU_ + 1024 + d4) : zero;

#pragma unroll 4
    for (int i = 0; i < 32; i++) {
        float4 u0c = *(const float4*)(ub + (size_t)i * NU_ + d4);
        float4 u2c = *(const float4*)(ub + (size_t)i * NU_ + 1024 + d4);
        const float* p0a = &u0a.x; const float* p0b = &u0b.x; const float* p0c = &u0c.x;
        const float* p2a = &u2a.x; const float* p2b = &u2b.x; const float* p2c = &u2c.x;

        __half h[4];
#pragma unroll
        for (int j = 0; j < 4; j++) {
            float s0 = c0t[0][j] * p0a[j] + c0t[1][j] * p0b[j] + c0t[2][j] * p0c[j] + b0v[j];
            float s2 = c2t[0][j] * p2a[j] + c2t[1][j] * p2b[j] + c2t[2][j] * p2c[j] + b2v[j];
            float z = s0 * s0 * s2 * fbv[j];
            h[j] = __float2half(z);
        }
        const size_t o = ((size_t)(b * L_ + l0 + i)) * 1024 + d4;
        *(uint2*)(g_Zth + o) = *(uint2*)h;

        u0a = u0b; u0b = u0c;
        u2a = u2b; u2b = u2c;
    }
}

// =====================================================================
// SLOW PATH (h != 0) — correctness fallback merged into ONE kernel.
// Inactive for this benchmark (h==0) — exits immediately.
// =====================================================================
__global__ __launch_bounds__(256)
void slow_path_kernel(const float* __restrict__ wc, const float* __restrict__ bc,
                      const float* __restrict__ fb) {
    if (g_hnz == 0) return;
    const int row = blockIdx.x;          // b*D + d
    const int b = row >> 10;
    const int d = row & (D_ - 1);
    const int d2 = d + 2048;
    const float c00 = wc[d * 3], c01 = wc[d * 3 + 1], c02 = wc[d * 3 + 2];
    const float c20 = wc[d2 * 3], c21 = wc[d2 * 3 + 1], c22 = wc[d2 * 3 + 2];
    const float b0v = bc[d], b2v = bc[d2], fbd = fb[d];

    __shared__ float hs[1024];
    __shared__ float s0s[4096];
    __shared__ float vs[1040 + 4096];    // 1040 leading zeros = causal padding

    for (int i = threadIdx.x; i < 1024; i += 256) hs[i] = g_h[i];
    for (int i = threadIdx.x; i < 1040; i += 256) vs[i] = 0.f;

    const float* Ub = g_U + (size_t)(b * L_) * NU_;
    for (int l = threadIdx.x; l < L_; l += 256) {
        float u0c = Ub[(size_t)l * NU_ + d];
        float u2c = Ub[(size_t)l * NU_ + 1024 + d];
        float u0b = (l >= 1) ? Ub[(size_t)(l - 1) * NU_ + d] : 0.f;
        float u2b = (l >= 1) ? Ub[(size_t)(l - 1) * NU_ + 1024 + d] : 0.f;
        float u0a = (l >= 2) ? Ub[(size_t)(l - 2) * NU_ + d] : 0.f;
        float u2a = (l >= 2) ? Ub[(size_t)(l - 2) * NU_ + 1024 + d] : 0.f;
        float s0 = c00 * u0a + c01 * u0b + c02 * u0c + b0v;
        float s2 = c20 * u2a + c21 * u2b + c22 * u2c + b2v;
        s0s[l] = s0;
        vs[1040 + l] = s0 * s2;
    }
    __syncthreads();

    const int l0 = threadIdx.x * 16;
    float acc[16];
#pragma unroll
    for (int i = 0; i < 16; i++) acc[i] = 0.f;
#pragma unroll 1
    for (int j0 = 0; j0 < 1024; j0 += 16) {
        float hh[16];
#pragma unroll
        for (int jj = 0; jj < 16; jj++) hh[jj] = hs[j0 + jj];
        float w[31];
        const int base = 1040 + l0 - j0 - 15;
#pragma unroll
        for (int k = 0; k < 31; k++) w[k] = vs[base + k];
#pragma unroll
        for (int i = 0; i < 16; i++)
#pragma unroll
            for (int jj = 0; jj < 16; jj++)
                acc[i] += hh[jj] * w[15 + i - jj];
    }
#pragma unroll
    for (int i = 0; i < 16; i++) {
        const int l = l0 + i;
        const float z = (acc[i] + vs[1040 + l] * fbd) * s0s[l];
        g_Zth[((size_t)(b * L_ + l)) * 1024 + d] = __float2half(z);
    }
}

// =====================================================================
extern "C" void kernel_launch(void* const* d_in, const int* in_sizes, int n_in,
                              void* d_out, int out_size) {
    const float* x      = (const float*)d_in[0];
    const float* w_in   = (const float*)d_in[1];
    const float* b_in   = (const float*)d_in[2];
    const float* w_conv = (const float*)d_in[3];
    const float* b_conv = (const float*)d_in[4];
    // d_in[5] = w1 (multiplied by t[0]==0; unused for filters[0])
    const float* b1     = (const float*)d_in[6];
    const float* w2     = (const float*)d_in[7];
    const float* b2     = (const float*)d_in[8];
    const float* w3     = (const float*)d_in[9];
    const float* fbias  = (const float*)d_in[10];
    const float* w_out  = (const float*)d_in[11];
    const float* b_out  = (const float*)d_in[12];
    float* out = (float*)d_out;

    split_x_kernel<<<BL_ * D_ / 1024, 256>>>(x);
    prep_w_all<<<dim3(96, 32), dim3(32, 8)>>>(w_in, w_out);
    filtgen_kernel<<<1, 1024>>>(b1, w2, b2, w3, b_in);

    gemm_mma<0, 128><<<dim3(NU_ / 128, BL_ / 128), 256>>>(nullptr, nullptr);

    // slow path (no-op when h == 0)
    slow_path_kernel<<<B_ * D_, 256>>>(w_conv, b_conv, fbias);
    // fast path (no-op when h != 0)
    fuse_fast_kernel<<<dim3(L_ / 32, B_), 256>>>(w_conv, b_conv, fbias);

    gemm_mma<1, 64><<<dim3(1024 / 128, BL_ / 64), 256>>>(b_out, out);
}

// round 16
// speedup vs baseline: 1.5325x; 1.0009x over previous
#include <cuda_runtime.h>
#include <cuda_fp16.h>
#include <cstdint>

#define B_  2
#define L_  4096
#define D_  1024
#define BL_ 8192        // B_*L_
#define NU_ 2048        // kept columns of GEMM1 (stream0 + stream2)

// ---------------- scratch (static device globals; no allocation) ----------------
__device__ float g_U [(size_t)BL_ * NU_];        // GEMM1 out: [b*L+l][2048] fp32
__device__ float g_h [D_];
__device__ int   g_hnz;
__device__ __half g_Xh [(size_t)BL_ * D_];   // x rounded to fp16
__device__ __half g_Zth[(size_t)BL_ * D_];   // z (as [m][k]) fp16
__device__ __half g_W1 [(size_t)NU_ * D_];   // w_in kept cols, [n][k], fp16
__device__ __half g_W2 [(size_t)D_ * D_];    // w_out, [n][k], fp16
__device__ float g_biasg[NU_];

// ---------------- PTX helpers (arch-generic: sm_80+ features only) ----------------
__device__ __forceinline__ uint32_t smem_u32(const void* p) {
    uint32_t a;
    asm("{ .reg .u64 t; cvta.to.shared.u64 t, %1; cvt.u32.u64 %0, t; }" : "=r"(a) : "l"(p));
    return a;
}
__device__ __forceinline__ uint32_t swz(uint32_t o) { return o ^ ((o >> 3) & 0x70); }
__device__ __forceinline__ void cp16(uint32_t s, const void* g) {
    asm volatile("cp.async.cg.shared.global [%0], [%1], 16;" :: "r"(s), "l"(g));
}
__device__ __forceinline__ void cp_commit() {
    asm volatile("cp.async.commit_group;");
}
template <int N>
__device__ __forceinline__ void cp_wait() {
    asm volatile("cp.async.wait_group %0;" :: "n"(N));
}
__device__ __forceinline__ void ldsm4(uint32_t& r0, uint32_t& r1, uint32_t& r2, uint32_t& r3,
                                      uint32_t addr) {
    asm volatile("ldmatrix.sync.aligned.m8n8.x4.shared.b16 {%0,%1,%2,%3}, [%4];"
                 : "=r"(r0), "=r"(r1), "=r"(r2), "=r"(r3) : "r"(addr));
}
__device__ __forceinline__ void mma16816(float& c0, float& c1, float& c2, float& c3,
                                         uint32_t a0, uint32_t a1, uint32_t a2, uint32_t a3,
                                         uint32_t b0, uint32_t b1) {
    asm volatile("mma.sync.aligned.m16n8k16.row.col.f32.f16.f16.f32 "
                 "{%0,%1,%2,%3}, {%4,%5,%6,%7}, {%8,%9}, {%0,%1,%2,%3};"
                 : "+f"(c0), "+f"(c1), "+f"(c2), "+f"(c3)
                 : "r"(a0), "r"(a1), "r"(a2), "r"(a3), "r"(b0), "r"(b1));
}

// =====================================================================
// fp16 single-pass GEMM via ldmatrix + mma.sync (HMMA).
//   C = A*B (+bias), both operands fp16 (audited total rel_err ~5.3e-4).
// BK=64 chunks (16 iters), SW128 XOR-swizzled smem.
// 3-STAGE, DEPTH-2 cp.async pipeline: preload chunks 0,1; per iteration
// cp_wait<1> (current chunk landed, next still in flight), one
// __syncthreads, prefetch kc+2 into the stage freed last iteration.
// Single-pass chunks are short (~500cyc) — depth-1 exposed LDG latency
// (tensor fell to 65%); depth-2 re-covers it.
// TM=128: 8 warps 4(m)x2(n), warp tile 32x64, 2 CTAs/SM  (GEMM1).
// TM=64 : 8 warps 2(m)x4(n), warp tile 32x32, 3 CTAs/SM  (GEMM2).
// =====================================================================
template <int WHICH, int TM>
__global__ __launch_bounds__(256, TM == 128 ? 2 : 3)
void gemm_mma(const float* __restrict__ bias_p, float* __restrict__ C_p) {
    constexpr int WM_CNT = (TM == 128) ? 4 : 2;     // warps along M
    constexpr int WT_N   = 128 / (8 / WM_CNT);      // warp tile N (64 or 32)
    constexpr int NI     = WT_N / 8;                // n-frags per warp (8 or 4)
    constexpr int ATILE_B = TM * 128;               // bytes per A tile
    constexpr int BTILE_B = 16384;                  // 128x64 fp16
    constexpr int STAGE_H = (ATILE_B + BTILE_B) / 2;

    __shared__ __align__(1024) __half sm[3][STAGE_H];   // A|B per stage

    const int tid = threadIdx.x;
    const int lane = tid & 31;
    const int wid = tid >> 5;
    const int warp_m = wid % WM_CNT;
    const int warp_n = wid / WM_CNT;
    const int m0 = blockIdx.y * TM;
    const int n0 = blockIdx.x * 128;

    const __half* __restrict__ Ag = WHICH ? g_Zth : g_Xh;
    const __half* __restrict__ Bw = WHICH ? g_W2 : g_W1;
    const float* __restrict__ bias = WHICH ? bias_p : g_biasg;
    float* __restrict__ C = WHICH ? C_p : g_U;
    const int ldc = WHICH ? 1024 : 2048;

    uint32_t s0 = smem_u32(sm[0]);      // compute stage
    uint32_t s1 = smem_u32(sm[1]);      // next (in flight)
    uint32_t s2 = smem_u32(sm[2]);      // prefetch target (freed last iter)

    float acc[2][NI][4];
#pragma unroll
    for (int i = 0; i < 2; i++)
#pragma unroll
        for (int j = 0; j < NI; j++)
#pragma unroll
            for (int q = 0; q < 4; q++) acc[i][j][q] = 0.f;

    // ldmatrix lane->local-row maps
    const int a_loc = (lane & 7) + ((lane >> 3) & 1) * 8;   // m0k0,m8k0,m0k8,m8k8
    const int a_kb  = (lane >> 4) * 16;                     // bytes
    const int b_loc = (lane & 7) + ((lane >> 4) & 1) * 8;   // n0k0,n0k8,n8k0,n8k8
    const int b_kb  = ((lane >> 3) & 1) * 16;               // bytes

    auto load_chunk = [&](uint32_t dst, int k0) {
#pragma unroll
        for (int j = 0; j < TM / 32; j++) {                 // A tile (TM rows)
            const int id = tid + j * 256;
            const int row = id >> 3, seg = id & 7;
            cp16(dst + swz(row * 128 + seg * 16),
                 Ag + (size_t)(m0 + row) * 1024 + k0 + seg * 8);
        }
#pragma unroll
        for (int j = 0; j < 4; j++) {                       // B tile (128 rows)
            const int id = tid + j * 256;
            const int row = id >> 3, seg = id & 7;
            cp16(dst + ATILE_B + swz(row * 128 + seg * 16),
                 Bw + (size_t)(n0 + row) * 1024 + k0 + seg * 8);
        }
        cp_commit();
    };

    load_chunk(s0, 0);
    load_chunk(s1, 64);

#pragma unroll 1
    for (int kc = 0; kc < 16; kc++) {
        if (kc < 15) cp_wait<1>();       // chunk kc landed; kc+1 may be in flight
        else         cp_wait<0>();
        __syncthreads();                 // publish chunk kc; frees stage computed at kc-1

        if (kc + 2 < 16) load_chunk(s2, (kc + 2) * 64);

#pragma unroll
        for (int kk = 0; kk < 4; kk++) {
            const uint32_t kbase = kk * 32;           // bytes within 128B row
            uint32_t bh[NI][2];
#pragma unroll
            for (int nj = 0; nj < NI / 2; nj++) {
                uint32_t r0, r1, r2, r3;
                ldsm4(r0, r1, r2, r3, s0 + ATILE_B
                      + swz((warp_n * WT_N + nj * 16 + b_loc) * 128 + kbase + b_kb));
                bh[nj * 2 + 0][0] = r0; bh[nj * 2 + 0][1] = r1;
                bh[nj * 2 + 1][0] = r2; bh[nj * 2 + 1][1] = r3;
            }
            uint32_t a[2][4];
#pragma unroll
            for (int mi = 0; mi < 2; mi++)
                ldsm4(a[mi][0], a[mi][1], a[mi][2], a[mi][3],
                      s0 + swz((warp_m * 32 + mi * 16 + a_loc) * 128 + kbase + a_kb));
#pragma unroll
            for (int mi = 0; mi < 2; mi++)
#pragma unroll
                for (int ni = 0; ni < NI; ni++)
                    mma16816(acc[mi][ni][0], acc[mi][ni][1], acc[mi][ni][2], acc[mi][ni][3],
                             a[mi][0], a[mi][1], a[mi][2], a[mi][3], bh[ni][0], bh[ni][1]);
        }
        const uint32_t tmp = s0; s0 = s1; s1 = s2; s2 = tmp;   // rotate
    }

    // ---- epilogue: m16n8 C frag: c0,c1 @ (lane>>2, (lane&3)*2), c2,c3 @ row+8
    const int er = lane >> 2;
    const int ec = (lane & 3) * 2;
#pragma unroll
    for (int mi = 0; mi < 2; mi++) {
#pragma unroll
        for (int ni = 0; ni < NI; ni++) {
            const int row = m0 + warp_m * 32 + mi * 16 + er;
            const int col = n0 + warp_n * WT_N + ni * 8 + ec;
            float2 o0 = make_float2(acc[mi][ni][0] + bias[col], acc[mi][ni][1] + bias[col + 1]);
            float2 o1 = make_float2(acc[mi][ni][2] + bias[col], acc[mi][ni][3] + bias[col + 1]);
            *(float2*)&C[(size_t)row * ldc + col] = o0;
            *(float2*)&C[(size_t)(row + 8) * ldc + col] = o1;
        }
    }
}

// =====================================================================
// MERGED operand prep: x->fp16 round AND both weight transposes+rounds.
// blockIdx.x < 8192             : split_x slice (256 thr x 4 elems)
// blockIdx.x in [8192, 8192+3072): weight tile; w = bx-8192,
//   wn = w % 96 (n-tile: <64 -> w_in, else w_out), wk = w / 96 (k-tile)
// =====================================================================
__global__ __launch_bounds__(256)
void prep_all_kernel(const float* __restrict__ x,
                     const float* __restrict__ w_in, const float* __restrict__ w_out) {
    const int bx = blockIdx.x;
    if (bx < 8192) {
        const size_t i4 = ((size_t)bx * 256 + threadIdx.x) * 4;
        float4 v = *(const float4*)(x + i4);
        __half h[4];
        h[0] = __float2half(v.x); h[1] = __float2half(v.y);
        h[2] = __float2half(v.z); h[3] = __float2half(v.w);
        *(uint2*)(g_Xh + i4) = *(uint2*)h;
        return;
    }
    const int w = bx - 8192;
    const int wn = w % 96, wk = w / 96;
    const bool is1 = (wn < 64);
    const float* __restrict__ W = is1 ? w_in : w_out;
    __half* __restrict__ o = is1 ? g_W1 : g_W2;
    const int src_ld = is1 ? 3072 : 1024;
    const int n0 = (is1 ? wn : wn - 64) * 32;
    const int cbase = n0 + ((is1 && n0 >= 1024) ? 1024 : 0);
    const int k0 = wk * 32;
    __shared__ float t[32][33];
    const int tx = threadIdx.x & 31, ty = threadIdx.x >> 5;
#pragma unroll
    for (int j = 0; j < 4; j++)
        t[ty + 8 * j][tx] = W[(size_t)(k0 + ty + 8 * j) * src_ld + cbase + tx];
    __syncthreads();
#pragma unroll
    for (int j = 0; j < 4; j++)
        o[(size_t)(n0 + ty + 8 * j) * 1024 + k0 + tx] = __float2half(t[tx][ty + 8 * j]);
}

// =====================================================================
// Filter generation (row 0 only; t[0]==0 so w1 drops out) + bias gather
// =====================================================================
__device__ __forceinline__ float silu_f(float v) { return v / (1.f + __expf(-v)); }

__global__ void filtgen_kernel(const float* __restrict__ b1, const float* __restrict__ w2,
                               const float* __restrict__ b2, const float* __restrict__ w3,
                               const float* __restrict__ b_in) {
    __shared__ float m1[64], m2[64];
    __shared__ int flag;
    const int t = threadIdx.x;          // 1024 threads
    g_biasg[t] = b_in[t];
    g_biasg[t + 1024] = b_in[t + 2048];
    if (t == 0) flag = 0;
    if (t < 64) m1[t] = silu_f(b1[t]);
    __syncthreads();
    if (t < 64) {
        float a = b2[t];
#pragma unroll
        for (int i = 0; i < 64; i++) a += m1[i] * w2[i * 64 + t];
        m2[t] = silu_f(a);
    }
    __syncthreads();
    float a = 0.f;
#pragma unroll
    for (int j = 0; j < 64; j++) a += m2[j] * w3[j * 1024 + t];
    g_h[t] = a;
    if (a != 0.f) flag = 1;
    __syncthreads();
    if (t == 0) g_hnz = flag;
}

// =====================================================================
// FAST PATH (h == 0): fused depthwise conv + gate + pointwise "fir" +
// transpose-to-[m][k] + fp16 round, l-tiled register rotation.
// =====================================================================
__global__ __launch_bounds__(256)
void fuse_fast_kernel(const float* __restrict__ wc, const float* __restrict__ bc,
                      const float* __restrict__ fb) {
    if (g_hnz != 0) return;
    const int l0 = blockIdx.x * 32, b = blockIdx.y;
    const int d4 = threadIdx.x * 4;
    const float* ub = g_U + ((size_t)(b * L_ + l0)) * NU_;
    const float4 zero = make_float4(0.f, 0.f, 0.f, 0.f);

    float c0t[3][4], c2t[3][4], b0v[4], b2v[4], fbv[4];
#pragma unroll
    for (int j = 0; j < 4; j++) {
        const int d = d4 + j, d2 = d + 2048;
        c0t[0][j] = wc[d * 3]; c0t[1][j] = wc[d * 3 + 1]; c0t[2][j] = wc[d * 3 + 2];
        c2t[0][j] = wc[d2 * 3]; c2t[1][j] = wc[d2 * 3 + 1]; c2t[2][j] = wc[d2 * 3 + 2];
        b0v[j] = bc[d]; b2v[j] = bc[d2]; fbv[j] = fb[d];
    }

    float4 u0a = (l0 >= 2) ? *(const float4*)(ub - 2 * NU_ + d4) : zero;
    float4 u2a = (l0 >= 2) ? *(const float4*)(ub - 2 * NU_ + 1024 + d4) : zero;
    float4 u0b = (l0 >= 1) ? *(const float4*)(ub - NU_ + d4) : zero;
    float4 u2b = (l0 >= 1) ? *(const float4*)(ub - NU_ + 1024 + d4) : zero;

#pragma unroll 4
    for (int i = 0; i < 32; i++) {
        float4 u0c = *(const float4*)(ub + (size_t)i * NU_ + d4);
        float4 u2c = *(const float4*)(ub + (size_t)i * NU_ + 1024 + d4);
        const float* p0a = &u0a.x; const float* p0b = &u0b.x; const float* p0c = &u0c.x;
        const float* p2a = &u2a.x; const float* p2b = &u2b.x; const float* p2c = &u2c.x;

        __half h[4];
#pragma unroll
        for (int j = 0; j < 4; j++) {
            float s0 = c0t[0][j] * p0a[j] + c0t[1][j] * p0b[j] + c0t[2][j] * p0c[j] + b0v[j];
            float s2 = c2t[0][j] * p2a[j] + c2t[1][j] * p2b[j] + c2t[2][j] * p2c[j] + b2v[j];
            float z = s0 * s0 * s2 * fbv[j];
            h[j] = __float2half(z);
        }
        const size_t o = ((size_t)(b * L_ + l0 + i)) * 1024 + d4;
        *(uint2*)(g_Zth + o) = *(uint2*)h;

        u0a = u0b; u0b = u0c;
        u2a = u2b; u2b = u2c;
    }
}

// =====================================================================
// SLOW PATH (h != 0) — correctness fallback; no-op for this benchmark.
// =====================================================================
__global__ __launch_bounds__(256)
void slow_path_kernel(const float* __restrict__ wc, const float* __restrict__ bc,
                      const float* __restrict__ fb) {
    if (g_hnz == 0) return;
    const int row = blockIdx.x;          // b*D + d
    const int b = row >> 10;
    const int d = row & (D_ - 1);
    const int d2 = d + 2048;
    const float c00 = wc[d * 3], c01 = wc[d * 3 + 1], c02 = wc[d * 3 + 2];
    const float c20 = wc[d2 * 3], c21 = wc[d2 * 3 + 1], c22 = wc[d2 * 3 + 2];
    const float b0v = bc[d], b2v = bc[d2], fbd = fb[d];

    __shared__ float hs[1024];
    __shared__ float s0s[4096];
    __shared__ float vs[1040 + 4096];

    for (int i = threadIdx.x; i < 1024; i += 256) hs[i] = g_h[i];
    for (int i = threadIdx.x; i < 1040; i += 256) vs[i] = 0.f;

    const float* Ub = g_U + (size_t)(b * L_) * NU_;
    for (int l = threadIdx.x; l < L_; l += 256) {
        float u0c = Ub[(size_t)l * NU_ + d];
        float u2c = Ub[(size_t)l * NU_ + 1024 + d];
        float u0b = (l >= 1) ? Ub[(size_t)(l - 1) * NU_ + d] : 0.f;
        float u2b = (l >= 1) ? Ub[(size_t)(l - 1) * NU_ + 1024 + d] : 0.f;
        float u0a = (l >= 2) ? Ub[(size_t)(l - 2) * NU_ + d] : 0.f;
        float u2a = (l >= 2) ? Ub[(size_t)(l - 2) * NU_ + 1024 + d] : 0.f;
        float s0 = c00 * u0a + c01 * u0b + c02 * u0c + b0v;
        float s2 = c20 * u2a + c21 * u2b + c22 * u2c + b2v;
        s0s[l] = s0;
        vs[1040 + l] = s0 * s2;
    }
    __syncthreads();

    const int l0 = threadIdx.x * 16;
    float acc[16];
#pragma unroll
    for (int i = 0; i < 16; i++) acc[i] = 0.f;
#pragma unroll 1
    for (int j0 = 0; j0 < 1024; j0 += 16) {
        float hh[16];
#pragma unroll
        for (int jj = 0; jj < 16; jj++) hh[jj] = hs[j0 + jj];
        float w[31];
        const int base = 1040 + l0 - j0 - 15;
#pragma unroll
        for (int k = 0; k < 31; k++) w[k] = vs[base + k];
#pragma unroll
        for (int i = 0; i < 16; i++)
#pragma unroll
            for (int jj = 0; jj < 16; jj++)
                acc[i] += hh[jj] * w[15 + i - jj];
    }
#pragma unroll
    for (int i = 0; i < 16; i++) {
        const int l = l0 + i;
        const float z = (acc[i] + vs[1040 + l] * fbd) * s0s[l];
        g_Zth[((size_t)(b * L_ + l)) * 1024 + d] = __float2half(z);
    }
}

// =====================================================================
extern "C" void kernel_launch(void* const* d_in, const int* in_sizes, int n_in,
                              void* d_out, int out_size) {
    const float* x      = (const float*)d_in[0];
    const float* w_in   = (const float*)d_in[1];
    const float* b_in   = (const float*)d_in[2];
    const float* w_conv = (const float*)d_in[3];
    const float* b_conv = (const float*)d_in[4];
    // d_in[5] = w1 (multiplied by t[0]==0; unused for filters[0])
    const float* b1     = (const float*)d_in[6];
    const float* w2     = (const float*)d_in[7];
    const float* b2     = (const float*)d_in[8];
    const float* w3     = (const float*)d_in[9];
    const float* fbias  = (const float*)d_in[10];
    const float* w_out  = (const float*)d_in[11];
    const float* b_out  = (const float*)d_in[12];
    float* out = (float*)d_out;

    prep_all_kernel<<<8192 + 3072, 256>>>(x, w_in, w_out);
    filtgen_kernel<<<1, 1024>>>(b1, w2, b2, w3, b_in);

    gemm_mma<0, 128><<<dim3(NU_ / 128, BL_ / 128), 256>>>(nullptr, nullptr);

    // slow path (no-op when h == 0)
    slow_path_kernel<<<B_ * D_, 256>>>(w_conv, b_conv, fbias);
    // fast path (no-op when h != 0)
    fuse_fast_kernel<<<dim3(L_ / 32, B_), 256>>>(w_conv, b_conv, fbias);

    gemm_mma<1, 64><<<dim3(1024 / 128, BL_ / 64), 256>>>(b_out, out);
}

// round 17
// speedup vs baseline: 1.5868x; 1.0355x over previous
#include <cuda_runtime.h>
#include <cuda_fp16.h>
#include <cstdint>

#define B_  2
#define L_  4096
#define D_  1024
#define BL_ 8192        // B_*L_
#define NU_ 2048        // kept columns of GEMM1 (stream0 + stream2)

// ---------------- scratch (static device globals; no allocation) ----------------
__device__ __half g_Uh [(size_t)BL_ * NU_];  // GEMM1 out, fp16 (audited)
__device__ float g_h [D_];
__device__ int   g_hnz;
__device__ __half g_Xh [(size_t)BL_ * D_];   // x rounded to fp16
__device__ __half g_Zth[(size_t)BL_ * D_];   // z (as [m][k]) fp16
__device__ __half g_W1 [(size_t)NU_ * D_];   // w_in kept cols, [n][k], fp16
__device__ __half g_W2 [(size_t)D_ * D_];    // w_out, [n][k], fp16
__device__ float g_biasg[NU_];

// ---------------- PTX helpers (arch-generic: sm_80+ features only) ----------------
__device__ __forceinline__ uint32_t smem_u32(const void* p) {
    uint32_t a;
    asm("{ .reg .u64 t; cvta.to.shared.u64 t, %1; cvt.u32.u64 %0, t; }" : "=r"(a) : "l"(p));
    return a;
}
__device__ __forceinline__ uint32_t swz(uint32_t o) { return o ^ ((o >> 3) & 0x70); }
__device__ __forceinline__ void cp16(uint32_t s, const void* g) {
    asm volatile("cp.async.cg.shared.global [%0], [%1], 16;" :: "r"(s), "l"(g));
}
__device__ __forceinline__ void cp_commit() {
    asm volatile("cp.async.commit_group;");
}
template <int N>
__device__ __forceinline__ void cp_wait() {
    asm volatile("cp.async.wait_group %0;" :: "n"(N));
}
__device__ __forceinline__ void ldsm4(uint32_t& r0, uint32_t& r1, uint32_t& r2, uint32_t& r3,
                                      uint32_t addr) {
    asm volatile("ldmatrix.sync.aligned.m8n8.x4.shared.b16 {%0,%1,%2,%3}, [%4];"
                 : "=r"(r0), "=r"(r1), "=r"(r2), "=r"(r3) : "r"(addr));
}
__device__ __forceinline__ void mma16816(float& c0, float& c1, float& c2, float& c3,
                                         uint32_t a0, uint32_t a1, uint32_t a2, uint32_t a3,
                                         uint32_t b0, uint32_t b1) {
    asm volatile("mma.sync.aligned.m16n8k16.row.col.f32.f16.f16.f32 "
                 "{%0,%1,%2,%3}, {%4,%5,%6,%7}, {%8,%9}, {%0,%1,%2,%3};"
                 : "+f"(c0), "+f"(c1), "+f"(c2), "+f"(c3)
                 : "r"(a0), "r"(a1), "r"(a2), "r"(a3), "r"(b0), "r"(b1));
}

// =====================================================================
// fp16 single-pass GEMM via ldmatrix + mma.sync (HMMA).
// 3-stage depth-2 cp.async pipeline, BK=64, SW128 swizzle, one barrier
// per chunk.  TM=128: 4(m)x2(n) warps, 2 CTAs/SM.  TM=64: 2x4, 3 CTAs/SM.
// WHICH=0: GEMM1 (Xh x W1 -> g_Uh FP16, bias g_biasg, ldc 2048)
// WHICH=1: GEMM2 (Zth x W2 -> out fp32, bias param,  ldc 1024)
// =====================================================================
template <int WHICH, int TM>
__global__ __launch_bounds__(256, TM == 128 ? 2 : 3)
void gemm_mma(const float* __restrict__ bias_p, float* __restrict__ C_p) {
    constexpr int WM_CNT = (TM == 128) ? 4 : 2;     // warps along M
    constexpr int WT_N   = 128 / (8 / WM_CNT);      // warp tile N (64 or 32)
    constexpr int NI     = WT_N / 8;                // n-frags per warp (8 or 4)
    constexpr int ATILE_B = TM * 128;               // bytes per A tile
    constexpr int BTILE_B = 16384;                  // 128x64 fp16
    constexpr int STAGE_H = (ATILE_B + BTILE_B) / 2;

    __shared__ __align__(1024) __half sm[3][STAGE_H];   // A|B per stage

    const int tid = threadIdx.x;
    const int lane = tid & 31;
    const int wid = tid >> 5;
    const int warp_m = wid % WM_CNT;
    const int warp_n = wid / WM_CNT;
    const int m0 = blockIdx.y * TM;
    const int n0 = blockIdx.x * 128;

    const __half* __restrict__ Ag = WHICH ? g_Zth : g_Xh;
    const __half* __restrict__ Bw = WHICH ? g_W2 : g_W1;
    const float* __restrict__ bias = WHICH ? bias_p : g_biasg;

    uint32_t s0 = smem_u32(sm[0]);      // compute stage
    uint32_t s1 = smem_u32(sm[1]);      // next (in flight)
    uint32_t s2 = smem_u32(sm[2]);      // prefetch target

    float acc[2][NI][4];
#pragma unroll
    for (int i = 0; i < 2; i++)
#pragma unroll
        for (int j = 0; j < NI; j++)
#pragma unroll
            for (int q = 0; q < 4; q++) acc[i][j][q] = 0.f;

    // ldmatrix lane->local-row maps
    const int a_loc = (lane & 7) + ((lane >> 3) & 1) * 8;   // m0k0,m8k0,m0k8,m8k8
    const int a_kb  = (lane >> 4) * 16;                     // bytes
    const int b_loc = (lane & 7) + ((lane >> 4) & 1) * 8;   // n0k0,n0k8,n8k0,n8k8
    const int b_kb  = ((lane >> 3) & 1) * 16;               // bytes

    auto load_chunk = [&](uint32_t dst, int k0) {
#pragma unroll
        for (int j = 0; j < TM / 32; j++) {                 // A tile (TM rows)
            const int id = tid + j * 256;
            const int row = id >> 3, seg = id & 7;
            cp16(dst + swz(row * 128 + seg * 16),
                 Ag + (size_t)(m0 + row) * 1024 + k0 + seg * 8);
        }
#pragma unroll
        for (int j = 0; j < 4; j++) {                       // B tile (128 rows)
            const int id = tid + j * 256;
            const int row = id >> 3, seg = id & 7;
            cp16(dst + ATILE_B + swz(row * 128 + seg * 16),
                 Bw + (size_t)(n0 + row) * 1024 + k0 + seg * 8);
        }
        cp_commit();
    };

    load_chunk(s0, 0);
    load_chunk(s1, 64);

#pragma unroll 1
    for (int kc = 0; kc < 16; kc++) {
        if (kc < 15) cp_wait<1>();
        else         cp_wait<0>();
        __syncthreads();

        if (kc + 2 < 16) load_chunk(s2, (kc + 2) * 64);

#pragma unroll
        for (int kk = 0; kk < 4; kk++) {
            const uint32_t kbase = kk * 32;
            uint32_t bh[NI][2];
#pragma unroll
            for (int nj = 0; nj < NI / 2; nj++) {
                uint32_t r0, r1, r2, r3;
                ldsm4(r0, r1, r2, r3, s0 + ATILE_B
                      + swz((warp_n * WT_N + nj * 16 + b_loc) * 128 + kbase + b_kb));
                bh[nj * 2 + 0][0] = r0; bh[nj * 2 + 0][1] = r1;
                bh[nj * 2 + 1][0] = r2; bh[nj * 2 + 1][1] = r3;
            }
            uint32_t a[2][4];
#pragma unroll
            for (int mi = 0; mi < 2; mi++)
                ldsm4(a[mi][0], a[mi][1], a[mi][2], a[mi][3],
                      s0 + swz((warp_m * 32 + mi * 16 + a_loc) * 128 + kbase + a_kb));
#pragma unroll
            for (int mi = 0; mi < 2; mi++)
#pragma unroll
                for (int ni = 0; ni < NI; ni++)
                    mma16816(acc[mi][ni][0], acc[mi][ni][1], acc[mi][ni][2], acc[mi][ni][3],
                             a[mi][0], a[mi][1], a[mi][2], a[mi][3], bh[ni][0], bh[ni][1]);
        }
        const uint32_t tmp = s0; s0 = s1; s1 = s2; s2 = tmp;
    }

    // ---- epilogue: m16n8 C frag: c0,c1 @ (lane>>2, (lane&3)*2), c2,c3 @ row+8
    const int er = lane >> 2;
    const int ec = (lane & 3) * 2;
#pragma unroll
    for (int mi = 0; mi < 2; mi++) {
#pragma unroll
        for (int ni = 0; ni < NI; ni++) {
            const int row = m0 + warp_m * 32 + mi * 16 + er;
            const int col = n0 + warp_n * WT_N + ni * 8 + ec;
            const float bc0 = bias[col], bc1 = bias[col + 1];
            if (WHICH == 0) {           // fp16 output to g_Uh
                __half2 h0 = __floats2half2_rn(acc[mi][ni][0] + bc0, acc[mi][ni][1] + bc1);
                __half2 h1 = __floats2half2_rn(acc[mi][ni][2] + bc0, acc[mi][ni][3] + bc1);
                *(__half2*)&g_Uh[(size_t)row * 2048 + col] = h0;
                *(__half2*)&g_Uh[(size_t)(row + 8) * 2048 + col] = h1;
            } else {                    // fp32 output to harness buffer
                float2 o0 = make_float2(acc[mi][ni][0] + bc0, acc[mi][ni][1] + bc1);
                float2 o1 = make_float2(acc[mi][ni][2] + bc0, acc[mi][ni][3] + bc1);
                *(float2*)&C_p[(size_t)row * 1024 + col] = o0;
                *(float2*)&C_p[(size_t)(row + 8) * 1024 + col] = o1;
            }
        }
    }
}

// =====================================================================
// MERGED prep: x->fp16, both weight transposes, filter-gen, bias gather.
// bx <  8192             : x slice
// bx in [8192, 8192+3072): weight tile
// bx == 8192+3072        : filtgen + bias gather (256 thr, 4 outputs each)
// =====================================================================
__device__ __forceinline__ float silu_f(float v) { return v / (1.f + __expf(-v)); }

__global__ __launch_bounds__(256)
void prep_all_kernel(const float* __restrict__ x,
                     const float* __restrict__ w_in, const float* __restrict__ w_out,
                     const float* __restrict__ b1, const float* __restrict__ w2,
                     const float* __restrict__ b2, const float* __restrict__ w3,
                     const float* __restrict__ b_in) {
    const int bx = blockIdx.x;
    if (bx < 8192) {
        const size_t i4 = ((size_t)bx * 256 + threadIdx.x) * 4;
        float4 v = *(const float4*)(x + i4);
        __half h[4];
        h[0] = __float2half(v.x); h[1] = __float2half(v.y);
        h[2] = __float2half(v.z); h[3] = __float2half(v.w);
        *(uint2*)(g_Xh + i4) = *(uint2*)h;
        return;
    }
    if (bx < 8192 + 3072) {
        const int w = bx - 8192;
        const int wn = w % 96, wk = w / 96;
        const bool is1 = (wn < 64);
        const float* __restrict__ W = is1 ? w_in : w_out;
        __half* __restrict__ o = is1 ? g_W1 : g_W2;
        const int src_ld = is1 ? 3072 : 1024;
        const int n0 = (is1 ? wn : wn - 64) * 32;
        const int cbase = n0 + ((is1 && n0 >= 1024) ? 1024 : 0);
        const int k0 = wk * 32;
        __shared__ float t[32][33];
        const int tx = threadIdx.x & 31, ty = threadIdx.x >> 5;
#pragma unroll
        for (int j = 0; j < 4; j++)
            t[ty + 8 * j][tx] = W[(size_t)(k0 + ty + 8 * j) * src_ld + cbase + tx];
        __syncthreads();
#pragma unroll
        for (int j = 0; j < 4; j++)
            o[(size_t)(n0 + ty + 8 * j) * 1024 + k0 + tx] = __float2half(t[tx][ty + 8 * j]);
        return;
    }
    // ---- filtgen + bias gather (one block, 256 threads) ----
    __shared__ float m1[64], m2[64];
    __shared__ int flag;
    const int t = threadIdx.x;
#pragma unroll
    for (int j = 0; j < 4; j++) {
        const int i = t + 256 * j;
        g_biasg[i] = b_in[i];
        g_biasg[i + 1024] = b_in[i + 2048];
    }
    if (t == 0) flag = 0;
    if (t < 64) m1[t] = silu_f(b1[t]);
    __syncthreads();
    if (t < 64) {
        float a = b2[t];
#pragma unroll
        for (int i = 0; i < 64; i++) a += m1[i] * w2[i * 64 + t];
        m2[t] = silu_f(a);
    }
    __syncthreads();
    int any = 0;
#pragma unroll
    for (int c = 0; c < 4; c++) {
        const int i = t + 256 * c;
        float a = 0.f;
#pragma unroll
        for (int j = 0; j < 64; j++) a += m2[j] * w3[j * 1024 + i];
        g_h[i] = a;
        if (a != 0.f) any = 1;
    }
    if (any) flag = 1;
    __syncthreads();
    if (t == 0) g_hnz = flag;
}

// =====================================================================
// MERGED post-GEMM1 kernel (grid 2048 blocks, 256 thr):
// FAST (h==0): blocks 0..255 do conv+gate+pointwise+transpose+fp16 round,
//              reading g_Uh (fp16) once with register rotation.
// SLOW (h!=0): all 2048 blocks, one (b,d) row each: conv + 1024-tap FIR +
//              gate + transpose + fp16 round.
// =====================================================================
__global__ __launch_bounds__(256)
void post_kernel(const float* __restrict__ wc, const float* __restrict__ bc,
                 const float* __restrict__ fb) {
    if (g_hnz == 0) {
        if (blockIdx.x >= 256) return;
        const int l0 = (blockIdx.x & 127) * 32;
        const int b = blockIdx.x >> 7;
        const int d4 = threadIdx.x * 4;
        const __half* ub = g_Uh + ((size_t)(b * L_ + l0)) * NU_;

        float c0t[3][4], c2t[3][4], b0v[4], b2v[4], fbv[4];
#pragma unroll
        for (int j = 0; j < 4; j++) {
            const int d = d4 + j, d2 = d + 2048;
            c0t[0][j] = wc[d * 3]; c0t[1][j] = wc[d * 3 + 1]; c0t[2][j] = wc[d * 3 + 2];
            c2t[0][j] = wc[d2 * 3]; c2t[1][j] = wc[d2 * 3 + 1]; c2t[2][j] = wc[d2 * 3 + 2];
            b0v[j] = bc[d]; b2v[j] = bc[d2]; fbv[j] = fb[d];
        }

        auto ld4 = [](const __half* p) {
            uint2 r = *(const uint2*)p;
            float4 f;
            float2 lo = __half22float2(*(__half2*)&r.x);
            float2 hi = __half22float2(*(__half2*)&r.y);
            f.x = lo.x; f.y = lo.y; f.z = hi.x; f.w = hi.y;
            return f;
        };
        const float4 zero = make_float4(0.f, 0.f, 0.f, 0.f);
        float4 u0a = (l0 >= 2) ? ld4(ub - 2 * NU_ + d4) : zero;
        float4 u2a = (l0 >= 2) ? ld4(ub - 2 * NU_ + 1024 + d4) : zero;
        float4 u0b = (l0 >= 1) ? ld4(ub - NU_ + d4) : zero;
        float4 u2b = (l0 >= 1) ? ld4(ub - NU_ + 1024 + d4) : zero;

#pragma unroll 4
        for (int i = 0; i < 32; i++) {
            float4 u0c = ld4(ub + (size_t)i * NU_ + d4);
            float4 u2c = ld4(ub + (size_t)i * NU_ + 1024 + d4);
            const float* p0a = &u0a.x; const float* p0b = &u0b.x; const float* p0c = &u0c.x;
            const float* p2a = &u2a.x; const float* p2b = &u2b.x; const float* p2c = &u2c.x;

            __half h[4];
#pragma unroll
            for (int j = 0; j < 4; j++) {
                float s0 = c0t[0][j] * p0a[j] + c0t[1][j] * p0b[j] + c0t[2][j] * p0c[j] + b0v[j];
                float s2 = c2t[0][j] * p2a[j] + c2t[1][j] * p2b[j] + c2t[2][j] * p2c[j] + b2v[j];
                float z = s0 * s0 * s2 * fbv[j];
                h[j] = __float2half(z);
            }
            const size_t o = ((size_t)(b * L_ + l0 + i)) * 1024 + d4;
            *(uint2*)(g_Zth + o) = *(uint2*)h;

            u0a = u0b; u0b = u0c;
            u2a = u2b; u2b = u2c;
        }
        return;
    }

    // ---------------- SLOW PATH (h != 0) ----------------
    const int row = blockIdx.x;          // b*D + d
    const int b = row >> 10;
    const int d = row & (D_ - 1);
    const int d2 = d + 2048;
    const float c00 = wc[d * 3], c01 = wc[d * 3 + 1], c02 = wc[d * 3 + 2];
    const float c20 = wc[d2 * 3], c21 = wc[d2 * 3 + 1], c22 = wc[d2 * 3 + 2];
    const float b0v = bc[d], b2v = bc[d2], fbd = fb[d];

    __shared__ float hs[1024];
    __shared__ float s0s[4096];
    __shared__ float vs[1040 + 4096];

    for (int i = threadIdx.x; i < 1024; i += 256) hs[i] = g_h[i];
    for (int i = threadIdx.x; i < 1040; i += 256) vs[i] = 0.f;

    const __half* Ub = g_Uh + (size_t)(b * L_) * NU_;
    for (int l = threadIdx.x; l < L_; l += 256) {
        float u0c = __half2float(Ub[(size_t)l * NU_ + d]);
        float u2c = __half2float(Ub[(size_t)l * NU_ + 1024 + d]);
        float u0b = (l >= 1) ? __half2float(Ub[(size_t)(l - 1) * NU_ + d]) : 0.f;
        float u2b = (l >= 1) ? __half2float(Ub[(size_t)(l - 1) * NU_ + 1024 + d]) : 0.f;
        float u0a = (l >= 2) ? __half2float(Ub[(size_t)(l - 2) * NU_ + d]) : 0.f;
        float u2a = (l >= 2) ? __half2float(Ub[(size_t)(l - 2) * NU_ + 1024 + d]) : 0.f;
        float s0 = c00 * u0a + c01 * u0b + c02 * u0c + b0v;
        float s2 = c20 * u2a + c21 * u2b + c22 * u2c + b2v;
        s0s[l] = s0;
        vs[1040 + l] = s0 * s2;
    }
    __syncthreads();

    const int l0 = threadIdx.x * 16;
    float acc[16];
#pragma unroll
    for (int i = 0; i < 16; i++) acc[i] = 0.f;
#pragma unroll 1
    for (int j0 = 0; j0 < 1024; j0 += 16) {
        float hh[16];
#pragma unroll
        for (int jj = 0; jj < 16; jj++) hh[jj] = hs[j0 + jj];
        float w[31];
        const int base = 1040 + l0 - j0 - 15;
#pragma unroll
        for (int k = 0; k < 31; k++) w[k] = vs[base + k];
#pragma unroll
        for (int i = 0; i < 16; i++)
#pragma unroll
            for (int jj = 0; jj < 16; jj++)
                acc[i] += hh[jj] * w[15 + i - jj];
    }
#pragma unroll
    for (int i = 0; i < 16; i++) {
        const int l = l0 + i;
        const float z = (acc[i] + vs[1040 + l] * fbd) * s0s[l];
        g_Zth[((size_t)(b * L_ + l)) * 1024 + d] = __float2half(z);
    }
}

// =====================================================================
extern "C" void kernel_launch(void* const* d_in, const int* in_sizes, int n_in,
                              void* d_out, int out_size) {
    const float* x      = (const float*)d_in[0];
    const float* w_in   = (const float*)d_in[1];
    const float* b_in   = (const float*)d_in[2];
    const float* w_conv = (const float*)d_in[3];
    const float* b_conv = (const float*)d_in[4];
    // d_in[5] = w1 (multiplied by t[0]==0; unused for filters[0])
    const float* b1     = (const float*)d_in[6];
    const float* w2     = (const float*)d_in[7];
    const float* b2     = (const float*)d_in[8];
    const float* w3     = (const float*)d_in[9];
    const float* fbias  = (const float*)d_in[10];
    const float* w_out  = (const float*)d_in[11];
    const float* b_out  = (const float*)d_in[12];
    float* out = (float*)d_out;

    prep_all_kernel<<<8192 + 3072 + 1, 256>>>(x, w_in, w_out, b1, w2, b2, w3, b_in);

    gemm_mma<0, 128><<<dim3(NU_ / 128, BL_ / 128), 256>>>(nullptr, nullptr);

    post_kernel<<<B_ * D_, 256>>>(w_conv, b_conv, fbias);

    gemm_mma<1, 64><<<dim3(1024 / 128, BL_ / 64), 256>>>(b_out, out);
}